// round 6
// baseline (speedup 1.0000x reference)
#include <cuda_runtime.h>
#include <cuda_bf16.h>
#include <cstdint>

// Problem constants
#define BATCH 2
#define SEQ   2048
#define DIM   1024
#define HEADS 16
#define DK    64
#define CL    256
#define HID   512
#define MROWS (BATCH*SEQ)   // 4096

// ---------------- scratch (device globals; no allocation allowed) ----------------
__device__ float g_q[MROWS * DIM];
__device__ float g_k[MROWS * DIM];
__device__ float g_v[MROWS * DIM];
__device__ float g_x[MROWS * DIM];
__device__ float g_h[BATCH * HID];
__device__ float g_c[BATCH * DIM];

// ---------------- cond MLP ----------------
// h[b][j] = relu(sum_k cond[b][k] * Wc1[k][j] + bc1[j])
__global__ void cond_mlp1(const float* __restrict__ cond, const float* __restrict__ Wc1,
                          const float* __restrict__ bc1, float* __restrict__ h) {
    int b = blockIdx.x;
    int j = threadIdx.x;            // 512
    float acc = bc1[j];
    const float* cr = cond + b * CL;
    #pragma unroll 8
    for (int k = 0; k < CL; k++) acc = fmaf(cr[k], Wc1[k * HID + j], acc);
    h[b * HID + j] = acc > 0.f ? acc : 0.f;
}

// c[b][n] = sum_k h[b][k] * Wc2[k][n]
__global__ void cond_mlp2(const float* __restrict__ h, const float* __restrict__ Wc2,
                          float* __restrict__ c) {
    int b = blockIdx.x;
    int n = threadIdx.x;            // 1024
    float acc = 0.f;
    const float* hr = h + b * HID;
    #pragma unroll 8
    for (int k = 0; k < HID; k++) acc = fmaf(hr[k], Wc2[k * DIM + n], acc);
    c[b * DIM + n] = acc;
}

// ---------------- fp32 SGEMM: C[M,N] = A[M,K] @ W[K,N] + bias[n] (+ cb[row/S][n]) ----
#define GBM 128
#define GBN 128
#define GBK 8

__global__ __launch_bounds__(256, 2)
void sgemm_bias(const float* __restrict__ A, const float* __restrict__ W,
                const float* __restrict__ bias, const float* __restrict__ cb,
                float* __restrict__ C, int M, int N, int K, int S) {
    __shared__ float As[GBK][GBM + 4];   // [k][m], padded
    __shared__ float Bs[GBK][GBN];       // [k][n]

    const int tid  = threadIdx.x;        // 256
    const int trow = tid >> 4;           // 0..15
    const int tcol = tid & 15;           // 0..15
    const int bm = blockIdx.y * GBM;
    const int bn = blockIdx.x * GBN;

    const int arow = tid >> 1;           // 0..127
    const int acol = (tid & 1) << 2;     // 0 or 4
    const int brow = tid >> 5;           // 0..7
    const int bcol = (tid & 31) << 2;    // 0..124

    float acc[8][8];
    #pragma unroll
    for (int i = 0; i < 8; i++)
        #pragma unroll
        for (int j = 0; j < 8; j++) acc[i][j] = 0.f;

    for (int k0 = 0; k0 < K; k0 += GBK) {
        float4 av = *(const float4*)(A + (size_t)(bm + arow) * K + k0 + acol);
        As[acol + 0][arow] = av.x;
        As[acol + 1][arow] = av.y;
        As[acol + 2][arow] = av.z;
        As[acol + 3][arow] = av.w;
        float4 bv = *(const float4*)(W + (size_t)(k0 + brow) * N + bn + bcol);
        *(float4*)&Bs[brow][bcol] = bv;
        __syncthreads();

        #pragma unroll
        for (int k = 0; k < GBK; k++) {
            float ra[8], rb[8];
            #pragma unroll
            for (int i = 0; i < 8; i++) ra[i] = As[k][trow * 8 + i];
            #pragma unroll
            for (int j = 0; j < 8; j++) rb[j] = Bs[k][tcol * 8 + j];
            #pragma unroll
            for (int i = 0; i < 8; i++)
                #pragma unroll
                for (int j = 0; j < 8; j++)
                    acc[i][j] = fmaf(ra[i], rb[j], acc[i][j]);
        }
        __syncthreads();
    }

    #pragma unroll
    for (int i = 0; i < 8; i++) {
        const int row = bm + trow * 8 + i;
        const int batch = row / S;
        const float* cbr = cb ? (cb + (size_t)batch * N) : nullptr;
        #pragma unroll
        for (int j = 0; j < 8; j += 4) {
            const int col = bn + tcol * 8 + j;
            float4 o;
            o.x = acc[i][j + 0] + bias[col + 0];
            o.y = acc[i][j + 1] + bias[col + 1];
            o.z = acc[i][j + 2] + bias[col + 2];
            o.w = acc[i][j + 3] + bias[col + 3];
            if (cbr) {
                o.x += cbr[col + 0]; o.y += cbr[col + 1];
                o.z += cbr[col + 2]; o.w += cbr[col + 3];
            }
            *(float4*)(C + (size_t)row * N + col) = o;
        }
    }
}

// ---------------- flash attention (fp32, online softmax) ----------------
// Br=128 query rows per CTA, Bc=64 key rows per iteration, dk=64.
// 256 threads: ty=tid/16 owns 8 q-rows, tx=tid%16 owns 4 cols.
#define BR 128
#define BC 64
#define QP 65                    // smem pitch (floats)
#define FA_SMEM_FLOATS (BR*QP /*Q*/ + BC*QP /*K*/ + BC*QP /*V*/ + BR*QP /*P*/ + BR*17 /*red*/ + 3*BR)
#define FA_SMEM_BYTES  (FA_SMEM_FLOATS * 4)

__global__ __launch_bounds__(256, 2)
void flash_attn(const float* __restrict__ Qg, const float* __restrict__ Kg,
                const float* __restrict__ Vg, float* __restrict__ Og) {
    extern __shared__ float sm[];
    float* Qs   = sm;                    // [BR][QP]
    float* Ks   = Qs + BR * QP;          // [BC][QP]
    float* Vs   = Ks + BC * QP;          // [BC][QP]
    float* Ps   = Vs + BC * QP;          // [BR][QP]
    float* red  = Ps + BR * QP;          // [BR][17]
    float* mrow = red + BR * 17;         // [BR]
    float* lrow = mrow + BR;             // [BR]
    float* arow = lrow + BR;             // [BR]

    const int tid = threadIdx.x;
    const int ty = tid >> 4;             // 0..15
    const int tx = tid & 15;             // 0..15
    const int row0 = ty * 8;
    const int col0 = tx * 4;

    const int qb = blockIdx.x;           // 0..15
    const int bh = blockIdx.y;           // 0..31
    const int b = bh >> 4, h = bh & 15;
    const size_t base = (size_t)b * SEQ * DIM + h * DK;
    const int qbase = qb * BR;

    // load Q tile [BR x DK]
    #pragma unroll
    for (int i = 0; i < 8; i++) {
        int idx = tid + i * 256;         // 0..2047
        int r = idx >> 4;
        int c4 = (idx & 15) << 2;
        float4 v = *(const float4*)(Qg + base + (size_t)(qbase + r) * DIM + c4);
        float* d = Qs + r * QP + c4;
        d[0] = v.x; d[1] = v.y; d[2] = v.z; d[3] = v.w;
    }
    if (tid < BR) { mrow[tid] = -1e30f; lrow[tid] = 0.f; }

    float oacc[8][4];
    #pragma unroll
    for (int i = 0; i < 8; i++)
        #pragma unroll
        for (int j = 0; j < 4; j++) oacc[i][j] = 0.f;

    const float sc = 0.125f;             // 1/sqrt(64)

    for (int kb = 0; kb < SEQ / BC; kb++) {
        __syncthreads();                 // protect Ks/Vs reuse, cover first-iter Qs
        const int kbase = kb * BC;
        #pragma unroll
        for (int i = 0; i < 4; i++) {
            int idx = tid + i * 256;     // 0..1023
            int r = idx >> 4;
            int c4 = (idx & 15) << 2;
            float4 kv = *(const float4*)(Kg + base + (size_t)(kbase + r) * DIM + c4);
            float* kd = Ks + r * QP + c4;
            kd[0] = kv.x; kd[1] = kv.y; kd[2] = kv.z; kd[3] = kv.w;
            float4 vv = *(const float4*)(Vg + base + (size_t)(kbase + r) * DIM + c4);
            float* vd = Vs + r * QP + c4;
            vd[0] = vv.x; vd[1] = vv.y; vd[2] = vv.z; vd[3] = vv.w;
        }
        __syncthreads();

        // S = Q K^T (scaled later)
        float sacc[8][4];
        #pragma unroll
        for (int i = 0; i < 8; i++)
            #pragma unroll
            for (int j = 0; j < 4; j++) sacc[i][j] = 0.f;

        for (int d = 0; d < DK; d++) {
            float qv[8], kv[4];
            #pragma unroll
            for (int i = 0; i < 8; i++) qv[i] = Qs[(row0 + i) * QP + d];
            #pragma unroll
            for (int j = 0; j < 4; j++) kv[j] = Ks[(col0 + j) * QP + d];
            #pragma unroll
            for (int i = 0; i < 8; i++)
                #pragma unroll
                for (int j = 0; j < 4; j++)
                    sacc[i][j] = fmaf(qv[i], kv[j], sacc[i][j]);
        }

        // partial row max (of scaled scores)
        #pragma unroll
        for (int i = 0; i < 8; i++) {
            float mx = fmaxf(fmaxf(sacc[i][0], sacc[i][1]),
                             fmaxf(sacc[i][2], sacc[i][3]));
            red[(row0 + i) * 17 + tx] = mx * sc;
        }
        __syncthreads();
        if (tid < BR) {
            float mx = red[tid * 17];
            #pragma unroll
            for (int c = 1; c < 16; c++) mx = fmaxf(mx, red[tid * 17 + c]);
            float mold = mrow[tid];
            float mnew = fmaxf(mold, mx);
            mrow[tid] = mnew;
            arow[tid] = __expf(mold - mnew);
        }
        __syncthreads();

        // exp, write P to smem, partial row sums, rescale O
        #pragma unroll
        for (int i = 0; i < 8; i++) {
            const int r = row0 + i;
            const float mn = mrow[r];
            const float a  = arow[r];
            float rs = 0.f;
            #pragma unroll
            for (int j = 0; j < 4; j++) {
                float p = __expf(fmaf(sacc[i][j], sc, -mn));
                Ps[r * QP + col0 + j] = p;
                rs += p;
            }
            red[r * 17 + tx] = rs;
            #pragma unroll
            for (int j = 0; j < 4; j++) oacc[i][j] *= a;
        }
        __syncthreads();
        if (tid < BR) {
            float s0 = 0.f;
            #pragma unroll
            for (int c = 0; c < 16; c++) s0 += red[tid * 17 + c];
            lrow[tid] = lrow[tid] * arow[tid] + s0;
        }
        // no sync needed: O-gemm below touches only Ps (synced) and Vs

        // O += P V
        for (int k = 0; k < BC; k++) {
            float pv[8], vv[4];
            #pragma unroll
            for (int i = 0; i < 8; i++) pv[i] = Ps[(row0 + i) * QP + k];
            #pragma unroll
            for (int j = 0; j < 4; j++) vv[j] = Vs[k * QP + col0 + j];
            #pragma unroll
            for (int i = 0; i < 8; i++)
                #pragma unroll
                for (int j = 0; j < 4; j++)
                    oacc[i][j] = fmaf(pv[i], vv[j], oacc[i][j]);
        }
    }
    __syncthreads();                     // final lrow writes visible

    #pragma unroll
    for (int i = 0; i < 8; i++) {
        const int r = row0 + i;
        const float inv = 1.f / lrow[r];
        float4 o;
        o.x = oacc[i][0] * inv; o.y = oacc[i][1] * inv;
        o.z = oacc[i][2] * inv; o.w = oacc[i][3] * inv;
        *(float4*)(Og + base + (size_t)(qbase + r) * DIM + col0) = o;
    }
}

// ---------------- launcher ----------------
extern "C" void kernel_launch(void* const* d_in, const int* in_sizes, int n_in,
                              void* d_out, int out_size) {
    const float* query = (const float*)d_in[0];
    const float* key   = (const float*)d_in[1];
    const float* value = (const float*)d_in[2];
    const float* cond  = (const float*)d_in[3];
    const float* Wq = (const float*)d_in[4];
    const float* bq = (const float*)d_in[5];
    const float* Wk = (const float*)d_in[6];
    const float* bk = (const float*)d_in[7];
    const float* Wv = (const float*)d_in[8];
    const float* bv = (const float*)d_in[9];
    const float* Wo = (const float*)d_in[10];
    const float* bo = (const float*)d_in[11];
    const float* Wc1 = (const float*)d_in[12];
    const float* bc1 = (const float*)d_in[13];
    const float* Wc2 = (const float*)d_in[14];
    float* out = (float*)d_out;

    float *q, *k, *v, *x, *hb, *cb;
    cudaGetSymbolAddress((void**)&q,  g_q);
    cudaGetSymbolAddress((void**)&k,  g_k);
    cudaGetSymbolAddress((void**)&v,  g_v);
    cudaGetSymbolAddress((void**)&x,  g_x);
    cudaGetSymbolAddress((void**)&hb, g_h);
    cudaGetSymbolAddress((void**)&cb, g_c);

    cudaFuncSetAttribute(flash_attn, cudaFuncAttributeMaxDynamicSharedMemorySize,
                         FA_SMEM_BYTES);

    // cond MLP
    cond_mlp1<<<BATCH, HID>>>(cond, Wc1, bc1, hb);
    cond_mlp2<<<BATCH, DIM>>>(hb, Wc2, cb);

    // projections
    dim3 gg(DIM / GBN, MROWS / GBM);   // (8, 32)
    sgemm_bias<<<gg, 256>>>(query, Wq, bq, nullptr, q, MROWS, DIM, DIM, SEQ);
    sgemm_bias<<<gg, 256>>>(key,   Wk, bk, nullptr, k, MROWS, DIM, DIM, SEQ);
    sgemm_bias<<<gg, 256>>>(value, Wv, bv, cb,      v, MROWS, DIM, DIM, SEQ);

    // attention
    flash_attn<<<dim3(SEQ / BR, BATCH * HEADS), 256, FA_SMEM_BYTES>>>(q, k, v, x);

    // output projection
    sgemm_bias<<<gg, 256>>>(x, Wo, bo, nullptr, out, MROWS, DIM, DIM, SEQ);
}

// round 7
// speedup vs baseline: 1.0012x; 1.0012x over previous
#include <cuda_runtime.h>
#include <cuda_bf16.h>
#include <cstdint>

// Problem constants
#define BATCH 2
#define SEQ   2048
#define DIM   1024
#define HEADS 16
#define DK    64
#define CL    256
#define HID   512
#define MROWS (BATCH*SEQ)   // 4096

// ---------------- scratch (device globals; no allocation allowed) ----------------
__device__ float g_q[MROWS * DIM];
__device__ float g_k[MROWS * DIM];
__device__ float g_v[MROWS * DIM];
__device__ float g_x[MROWS * DIM];
__device__ float g_h[BATCH * HID];
__device__ float g_c[BATCH * DIM];

// ---------------- cond MLP ----------------
// h[b][j] = relu(sum_k cond[b][k] * Wc1[k][j] + bc1[j])
__global__ void cond_mlp1(const float* __restrict__ cond, const float* __restrict__ Wc1,
                          const float* __restrict__ bc1, float* __restrict__ h) {
    int b = blockIdx.x;
    int j = threadIdx.x;            // 512
    float acc = bc1[j];
    const float* cr = cond + b * CL;
    #pragma unroll 8
    for (int k = 0; k < CL; k++) acc = fmaf(cr[k], Wc1[k * HID + j], acc);
    h[b * HID + j] = acc > 0.f ? acc : 0.f;
}

// c[b][n] = sum_k h[b][k] * Wc2[k][n]
__global__ void cond_mlp2(const float* __restrict__ h, const float* __restrict__ Wc2,
                          float* __restrict__ c) {
    int b = blockIdx.x;
    int n = threadIdx.x;            // 1024
    float acc = 0.f;
    const float* hr = h + b * HID;
    #pragma unroll 8
    for (int k = 0; k < HID; k++) acc = fmaf(hr[k], Wc2[k * DIM + n], acc);
    c[b * DIM + n] = acc;
}

// ---------------- fp32 SGEMM: C[M,N] = A[M,K] @ W[K,N] + bias[n] (+ cb[row/S][n]) ----
#define GBM 128
#define GBN 128
#define GBK 8

__global__ __launch_bounds__(256, 2)
void sgemm_bias(const float* __restrict__ A, const float* __restrict__ W,
                const float* __restrict__ bias, const float* __restrict__ cb,
                float* __restrict__ C, int M, int N, int K, int S) {
    __shared__ float As[GBK][GBM + 4];   // [k][m], padded
    __shared__ float Bs[GBK][GBN];       // [k][n]

    const int tid  = threadIdx.x;        // 256
    const int trow = tid >> 4;           // 0..15
    const int tcol = tid & 15;           // 0..15
    const int bm = blockIdx.y * GBM;
    const int bn = blockIdx.x * GBN;

    const int arow = tid >> 1;           // 0..127
    const int acol = (tid & 1) << 2;     // 0 or 4
    const int brow = tid >> 5;           // 0..7
    const int bcol = (tid & 31) << 2;    // 0..124

    float acc[8][8];
    #pragma unroll
    for (int i = 0; i < 8; i++)
        #pragma unroll
        for (int j = 0; j < 8; j++) acc[i][j] = 0.f;

    for (int k0 = 0; k0 < K; k0 += GBK) {
        float4 av = *(const float4*)(A + (size_t)(bm + arow) * K + k0 + acol);
        As[acol + 0][arow] = av.x;
        As[acol + 1][arow] = av.y;
        As[acol + 2][arow] = av.z;
        As[acol + 3][arow] = av.w;
        float4 bv = *(const float4*)(W + (size_t)(k0 + brow) * N + bn + bcol);
        *(float4*)&Bs[brow][bcol] = bv;
        __syncthreads();

        #pragma unroll
        for (int k = 0; k < GBK; k++) {
            float ra[8], rb[8];
            #pragma unroll
            for (int i = 0; i < 8; i++) ra[i] = As[k][trow * 8 + i];
            #pragma unroll
            for (int j = 0; j < 8; j++) rb[j] = Bs[k][tcol * 8 + j];
            #pragma unroll
            for (int i = 0; i < 8; i++)
                #pragma unroll
                for (int j = 0; j < 8; j++)
                    acc[i][j] = fmaf(ra[i], rb[j], acc[i][j]);
        }
        __syncthreads();
    }

    #pragma unroll
    for (int i = 0; i < 8; i++) {
        const int row = bm + trow * 8 + i;
        const int batch = row / S;
        const float* cbr = cb ? (cb + (size_t)batch * N) : nullptr;
        #pragma unroll
        for (int j = 0; j < 8; j += 4) {
            const int col = bn + tcol * 8 + j;
            float4 o;
            o.x = acc[i][j + 0] + bias[col + 0];
            o.y = acc[i][j + 1] + bias[col + 1];
            o.z = acc[i][j + 2] + bias[col + 2];
            o.w = acc[i][j + 3] + bias[col + 3];
            if (cbr) {
                o.x += cbr[col + 0]; o.y += cbr[col + 1];
                o.z += cbr[col + 2]; o.w += cbr[col + 3];
            }
            *(float4*)(C + (size_t)row * N + col) = o;
        }
    }
}

// ---------------- flash attention (fp32, online softmax) ----------------
// Br=128 query rows per CTA, Bc=64 key rows per iteration, dk=64.
// 256 threads: ty=tid/16 owns 8 q-rows, tx=tid%16 owns 4 cols.
#define BR 128
#define BC 64
#define QP 65                    // smem pitch (floats)
#define FA_SMEM_FLOATS (BR*QP /*Q*/ + BC*QP /*K*/ + BC*QP /*V*/ + BR*QP /*P*/ + BR*17 /*red*/ + 3*BR)
#define FA_SMEM_BYTES  (FA_SMEM_FLOATS * 4)

__global__ __launch_bounds__(256, 2)
void flash_attn(const float* __restrict__ Qg, const float* __restrict__ Kg,
                const float* __restrict__ Vg, float* __restrict__ Og) {
    extern __shared__ float sm[];
    float* Qs   = sm;                    // [BR][QP]
    float* Ks   = Qs + BR * QP;          // [BC][QP]
    float* Vs   = Ks + BC * QP;          // [BC][QP]
    float* Ps   = Vs + BC * QP;          // [BR][QP]
    float* red  = Ps + BR * QP;          // [BR][17]
    float* mrow = red + BR * 17;         // [BR]
    float* lrow = mrow + BR;             // [BR]
    float* arow = lrow + BR;             // [BR]

    const int tid = threadIdx.x;
    const int ty = tid >> 4;             // 0..15
    const int tx = tid & 15;             // 0..15
    const int row0 = ty * 8;
    const int col0 = tx * 4;

    const int qb = blockIdx.x;           // 0..15
    const int bh = blockIdx.y;           // 0..31
    const int b = bh >> 4, h = bh & 15;
    const size_t base = (size_t)b * SEQ * DIM + h * DK;
    const int qbase = qb * BR;

    // load Q tile [BR x DK]
    #pragma unroll
    for (int i = 0; i < 8; i++) {
        int idx = tid + i * 256;         // 0..2047
        int r = idx >> 4;
        int c4 = (idx & 15) << 2;
        float4 v = *(const float4*)(Qg + base + (size_t)(qbase + r) * DIM + c4);
        float* d = Qs + r * QP + c4;
        d[0] = v.x; d[1] = v.y; d[2] = v.z; d[3] = v.w;
    }
    if (tid < BR) { mrow[tid] = -1e30f; lrow[tid] = 0.f; }

    float oacc[8][4];
    #pragma unroll
    for (int i = 0; i < 8; i++)
        #pragma unroll
        for (int j = 0; j < 4; j++) oacc[i][j] = 0.f;

    const float sc = 0.125f;             // 1/sqrt(64)

    for (int kb = 0; kb < SEQ / BC; kb++) {
        __syncthreads();                 // protect Ks/Vs reuse, cover first-iter Qs
        const int kbase = kb * BC;
        #pragma unroll
        for (int i = 0; i < 4; i++) {
            int idx = tid + i * 256;     // 0..1023
            int r = idx >> 4;
            int c4 = (idx & 15) << 2;
            float4 kv = *(const float4*)(Kg + base + (size_t)(kbase + r) * DIM + c4);
            float* kd = Ks + r * QP + c4;
            kd[0] = kv.x; kd[1] = kv.y; kd[2] = kv.z; kd[3] = kv.w;
            float4 vv = *(const float4*)(Vg + base + (size_t)(kbase + r) * DIM + c4);
            float* vd = Vs + r * QP + c4;
            vd[0] = vv.x; vd[1] = vv.y; vd[2] = vv.z; vd[3] = vv.w;
        }
        __syncthreads();

        // S = Q K^T (scaled later)
        float sacc[8][4];
        #pragma unroll
        for (int i = 0; i < 8; i++)
            #pragma unroll
            for (int j = 0; j < 4; j++) sacc[i][j] = 0.f;

        for (int d = 0; d < DK; d++) {
            float qv[8], kv[4];
            #pragma unroll
            for (int i = 0; i < 8; i++) qv[i] = Qs[(row0 + i) * QP + d];
            #pragma unroll
            for (int j = 0; j < 4; j++) kv[j] = Ks[(col0 + j) * QP + d];
            #pragma unroll
            for (int i = 0; i < 8; i++)
                #pragma unroll
                for (int j = 0; j < 4; j++)
                    sacc[i][j] = fmaf(qv[i], kv[j], sacc[i][j]);
        }

        // partial row max (of scaled scores)
        #pragma unroll
        for (int i = 0; i < 8; i++) {
            float mx = fmaxf(fmaxf(sacc[i][0], sacc[i][1]),
                             fmaxf(sacc[i][2], sacc[i][3]));
            red[(row0 + i) * 17 + tx] = mx * sc;
        }
        __syncthreads();
        if (tid < BR) {
            float mx = red[tid * 17];
            #pragma unroll
            for (int c = 1; c < 16; c++) mx = fmaxf(mx, red[tid * 17 + c]);
            float mold = mrow[tid];
            float mnew = fmaxf(mold, mx);
            mrow[tid] = mnew;
            arow[tid] = __expf(mold - mnew);
        }
        __syncthreads();

        // exp, write P to smem, partial row sums, rescale O
        #pragma unroll
        for (int i = 0; i < 8; i++) {
            const int r = row0 + i;
            const float mn = mrow[r];
            const float a  = arow[r];
            float rs = 0.f;
            #pragma unroll
            for (int j = 0; j < 4; j++) {
                float p = __expf(fmaf(sacc[i][j], sc, -mn));
                Ps[r * QP + col0 + j] = p;
                rs += p;
            }
            red[r * 17 + tx] = rs;
            #pragma unroll
            for (int j = 0; j < 4; j++) oacc[i][j] *= a;
        }
        __syncthreads();
        if (tid < BR) {
            float s0 = 0.f;
            #pragma unroll
            for (int c = 0; c < 16; c++) s0 += red[tid * 17 + c];
            lrow[tid] = lrow[tid] * arow[tid] + s0;
        }
        // no sync needed: O-gemm below touches only Ps (synced) and Vs

        // O += P V
        for (int k = 0; k < BC; k++) {
            float pv[8], vv[4];
            #pragma unroll
            for (int i = 0; i < 8; i++) pv[i] = Ps[(row0 + i) * QP + k];
            #pragma unroll
            for (int j = 0; j < 4; j++) vv[j] = Vs[k * QP + col0 + j];
            #pragma unroll
            for (int i = 0; i < 8; i++)
                #pragma unroll
                for (int j = 0; j < 4; j++)
                    oacc[i][j] = fmaf(pv[i], vv[j], oacc[i][j]);
        }
    }
    __syncthreads();                     // final lrow writes visible

    #pragma unroll
    for (int i = 0; i < 8; i++) {
        const int r = row0 + i;
        const float inv = 1.f / lrow[r];
        float4 o;
        o.x = oacc[i][0] * inv; o.y = oacc[i][1] * inv;
        o.z = oacc[i][2] * inv; o.w = oacc[i][3] * inv;
        *(float4*)(Og + base + (size_t)(qbase + r) * DIM + col0) = o;
    }
}

// ---------------- launcher ----------------
extern "C" void kernel_launch(void* const* d_in, const int* in_sizes, int n_in,
                              void* d_out, int out_size) {
    const float* query = (const float*)d_in[0];
    const float* key   = (const float*)d_in[1];
    const float* value = (const float*)d_in[2];
    const float* cond  = (const float*)d_in[3];
    const float* Wq = (const float*)d_in[4];
    const float* bq = (const float*)d_in[5];
    const float* Wk = (const float*)d_in[6];
    const float* bk = (const float*)d_in[7];
    const float* Wv = (const float*)d_in[8];
    const float* bv = (const float*)d_in[9];
    const float* Wo = (const float*)d_in[10];
    const float* bo = (const float*)d_in[11];
    const float* Wc1 = (const float*)d_in[12];
    const float* bc1 = (const float*)d_in[13];
    const float* Wc2 = (const float*)d_in[14];
    float* out = (float*)d_out;

    float *q, *k, *v, *x, *hb, *cb;
    cudaGetSymbolAddress((void**)&q,  g_q);
    cudaGetSymbolAddress((void**)&k,  g_k);
    cudaGetSymbolAddress((void**)&v,  g_v);
    cudaGetSymbolAddress((void**)&x,  g_x);
    cudaGetSymbolAddress((void**)&hb, g_h);
    cudaGetSymbolAddress((void**)&cb, g_c);

    cudaFuncSetAttribute(flash_attn, cudaFuncAttributeMaxDynamicSharedMemorySize,
                         FA_SMEM_BYTES);

    // cond MLP
    cond_mlp1<<<BATCH, HID>>>(cond, Wc1, bc1, hb);
    cond_mlp2<<<BATCH, DIM>>>(hb, Wc2, cb);

    // projections
    dim3 gg(DIM / GBN, MROWS / GBM);   // (8, 32)
    sgemm_bias<<<gg, 256>>>(query, Wq, bq, nullptr, q, MROWS, DIM, DIM, SEQ);
    sgemm_bias<<<gg, 256>>>(key,   Wk, bk, nullptr, k, MROWS, DIM, DIM, SEQ);
    sgemm_bias<<<gg, 256>>>(value, Wv, bv, cb,      v, MROWS, DIM, DIM, SEQ);

    // attention
    flash_attn<<<dim3(SEQ / BR, BATCH * HEADS), 256, FA_SMEM_BYTES>>>(q, k, v, x);

    // output projection
    sgemm_bias<<<gg, 256>>>(x, Wo, bo, nullptr, out, MROWS, DIM, DIM, SEQ);
}

// round 8
// speedup vs baseline: 1.0015x; 1.0003x over previous
#include <cuda_runtime.h>
#include <cuda_bf16.h>
#include <cstdint>

// Problem constants
#define BATCH 2
#define SEQ   2048
#define DIM   1024
#define HEADS 16
#define DK    64
#define CL    256
#define HID   512
#define MROWS (BATCH*SEQ)   // 4096

// ---------------- scratch (device globals; no allocation allowed) ----------------
__device__ float g_q[MROWS * DIM];
__device__ float g_k[MROWS * DIM];
__device__ float g_v[MROWS * DIM];
__device__ float g_x[MROWS * DIM];
__device__ float g_h[BATCH * HID];
__device__ float g_c[BATCH * DIM];

// ---------------- cond MLP ----------------
// h[b][j] = relu(sum_k cond[b][k] * Wc1[k][j] + bc1[j])
__global__ void cond_mlp1(const float* __restrict__ cond, const float* __restrict__ Wc1,
                          const float* __restrict__ bc1, float* __restrict__ h) {
    int b = blockIdx.x;
    int j = threadIdx.x;            // 512
    float acc = bc1[j];
    const float* cr = cond + b * CL;
    #pragma unroll 8
    for (int k = 0; k < CL; k++) acc = fmaf(cr[k], Wc1[k * HID + j], acc);
    h[b * HID + j] = acc > 0.f ? acc : 0.f;
}

// c[b][n] = sum_k h[b][k] * Wc2[k][n]
__global__ void cond_mlp2(const float* __restrict__ h, const float* __restrict__ Wc2,
                          float* __restrict__ c) {
    int b = blockIdx.x;
    int n = threadIdx.x;            // 1024
    float acc = 0.f;
    const float* hr = h + b * HID;
    #pragma unroll 8
    for (int k = 0; k < HID; k++) acc = fmaf(hr[k], Wc2[k * DIM + n], acc);
    c[b * DIM + n] = acc;
}

// ---------------- fp32 SGEMM: C[M,N] = A[M,K] @ W[K,N] + bias[n] (+ cb[row/S][n]) ----
#define GBM 128
#define GBN 128
#define GBK 8

__global__ __launch_bounds__(256, 2)
void sgemm_bias(const float* __restrict__ A, const float* __restrict__ W,
                const float* __restrict__ bias, const float* __restrict__ cb,
                float* __restrict__ C, int M, int N, int K, int S) {
    __shared__ float As[GBK][GBM + 4];   // [k][m], padded
    __shared__ float Bs[GBK][GBN];       // [k][n]

    const int tid  = threadIdx.x;        // 256
    const int trow = tid >> 4;           // 0..15
    const int tcol = tid & 15;           // 0..15
    const int bm = blockIdx.y * GBM;
    const int bn = blockIdx.x * GBN;

    const int arow = tid >> 1;           // 0..127
    const int acol = (tid & 1) << 2;     // 0 or 4
    const int brow = tid >> 5;           // 0..7
    const int bcol = (tid & 31) << 2;    // 0..124

    float acc[8][8];
    #pragma unroll
    for (int i = 0; i < 8; i++)
        #pragma unroll
        for (int j = 0; j < 8; j++) acc[i][j] = 0.f;

    for (int k0 = 0; k0 < K; k0 += GBK) {
        float4 av = *(const float4*)(A + (size_t)(bm + arow) * K + k0 + acol);
        As[acol + 0][arow] = av.x;
        As[acol + 1][arow] = av.y;
        As[acol + 2][arow] = av.z;
        As[acol + 3][arow] = av.w;
        float4 bv = *(const float4*)(W + (size_t)(k0 + brow) * N + bn + bcol);
        *(float4*)&Bs[brow][bcol] = bv;
        __syncthreads();

        #pragma unroll
        for (int k = 0; k < GBK; k++) {
            float ra[8], rb[8];
            #pragma unroll
            for (int i = 0; i < 8; i++) ra[i] = As[k][trow * 8 + i];
            #pragma unroll
            for (int j = 0; j < 8; j++) rb[j] = Bs[k][tcol * 8 + j];
            #pragma unroll
            for (int i = 0; i < 8; i++)
                #pragma unroll
                for (int j = 0; j < 8; j++)
                    acc[i][j] = fmaf(ra[i], rb[j], acc[i][j]);
        }
        __syncthreads();
    }

    #pragma unroll
    for (int i = 0; i < 8; i++) {
        const int row = bm + trow * 8 + i;
        const int batch = row / S;
        const float* cbr = cb ? (cb + (size_t)batch * N) : nullptr;
        #pragma unroll
        for (int j = 0; j < 8; j += 4) {
            const int col = bn + tcol * 8 + j;
            float4 o;
            o.x = acc[i][j + 0] + bias[col + 0];
            o.y = acc[i][j + 1] + bias[col + 1];
            o.z = acc[i][j + 2] + bias[col + 2];
            o.w = acc[i][j + 3] + bias[col + 3];
            if (cbr) {
                o.x += cbr[col + 0]; o.y += cbr[col + 1];
                o.z += cbr[col + 2]; o.w += cbr[col + 3];
            }
            *(float4*)(C + (size_t)row * N + col) = o;
        }
    }
}

// ---------------- flash attention (fp32, online softmax) ----------------
// Br=128 query rows per CTA, Bc=64 key rows per iteration, dk=64.
// 256 threads: ty=tid/16 owns 8 q-rows, tx=tid%16 owns 4 cols.
#define BR 128
#define BC 64
#define QP 65                    // smem pitch (floats)
#define FA_SMEM_FLOATS (BR*QP /*Q*/ + BC*QP /*K*/ + BC*QP /*V*/ + BR*QP /*P*/ + BR*17 /*red*/ + 3*BR)
#define FA_SMEM_BYTES  (FA_SMEM_FLOATS * 4)

__global__ __launch_bounds__(256, 2)
void flash_attn(const float* __restrict__ Qg, const float* __restrict__ Kg,
                const float* __restrict__ Vg, float* __restrict__ Og) {
    extern __shared__ float sm[];
    float* Qs   = sm;                    // [BR][QP]
    float* Ks   = Qs + BR * QP;          // [BC][QP]
    float* Vs   = Ks + BC * QP;          // [BC][QP]
    float* Ps   = Vs + BC * QP;          // [BR][QP]
    float* red  = Ps + BR * QP;          // [BR][17]
    float* mrow = red + BR * 17;         // [BR]
    float* lrow = mrow + BR;             // [BR]
    float* arow = lrow + BR;             // [BR]

    const int tid = threadIdx.x;
    const int ty = tid >> 4;             // 0..15
    const int tx = tid & 15;             // 0..15
    const int row0 = ty * 8;
    const int col0 = tx * 4;

    const int qb = blockIdx.x;           // 0..15
    const int bh = blockIdx.y;           // 0..31
    const int b = bh >> 4, h = bh & 15;
    const size_t base = (size_t)b * SEQ * DIM + h * DK;
    const int qbase = qb * BR;

    // load Q tile [BR x DK]
    #pragma unroll
    for (int i = 0; i < 8; i++) {
        int idx = tid + i * 256;         // 0..2047
        int r = idx >> 4;
        int c4 = (idx & 15) << 2;
        float4 v = *(const float4*)(Qg + base + (size_t)(qbase + r) * DIM + c4);
        float* d = Qs + r * QP + c4;
        d[0] = v.x; d[1] = v.y; d[2] = v.z; d[3] = v.w;
    }
    if (tid < BR) { mrow[tid] = -1e30f; lrow[tid] = 0.f; }

    float oacc[8][4];
    #pragma unroll
    for (int i = 0; i < 8; i++)
        #pragma unroll
        for (int j = 0; j < 4; j++) oacc[i][j] = 0.f;

    const float sc = 0.125f;             // 1/sqrt(64)

    for (int kb = 0; kb < SEQ / BC; kb++) {
        __syncthreads();                 // protect Ks/Vs reuse, cover first-iter Qs
        const int kbase = kb * BC;
        #pragma unroll
        for (int i = 0; i < 4; i++) {
            int idx = tid + i * 256;     // 0..1023
            int r = idx >> 4;
            int c4 = (idx & 15) << 2;
            float4 kv = *(const float4*)(Kg + base + (size_t)(kbase + r) * DIM + c4);
            float* kd = Ks + r * QP + c4;
            kd[0] = kv.x; kd[1] = kv.y; kd[2] = kv.z; kd[3] = kv.w;
            float4 vv = *(const float4*)(Vg + base + (size_t)(kbase + r) * DIM + c4);
            float* vd = Vs + r * QP + c4;
            vd[0] = vv.x; vd[1] = vv.y; vd[2] = vv.z; vd[3] = vv.w;
        }
        __syncthreads();

        // S = Q K^T (scaled later)
        float sacc[8][4];
        #pragma unroll
        for (int i = 0; i < 8; i++)
            #pragma unroll
            for (int j = 0; j < 4; j++) sacc[i][j] = 0.f;

        for (int d = 0; d < DK; d++) {
            float qv[8], kv[4];
            #pragma unroll
            for (int i = 0; i < 8; i++) qv[i] = Qs[(row0 + i) * QP + d];
            #pragma unroll
            for (int j = 0; j < 4; j++) kv[j] = Ks[(col0 + j) * QP + d];
            #pragma unroll
            for (int i = 0; i < 8; i++)
                #pragma unroll
                for (int j = 0; j < 4; j++)
                    sacc[i][j] = fmaf(qv[i], kv[j], sacc[i][j]);
        }

        // partial row max (of scaled scores)
        #pragma unroll
        for (int i = 0; i < 8; i++) {
            float mx = fmaxf(fmaxf(sacc[i][0], sacc[i][1]),
                             fmaxf(sacc[i][2], sacc[i][3]));
            red[(row0 + i) * 17 + tx] = mx * sc;
        }
        __syncthreads();
        if (tid < BR) {
            float mx = red[tid * 17];
            #pragma unroll
            for (int c = 1; c < 16; c++) mx = fmaxf(mx, red[tid * 17 + c]);
            float mold = mrow[tid];
            float mnew = fmaxf(mold, mx);
            mrow[tid] = mnew;
            arow[tid] = __expf(mold - mnew);
        }
        __syncthreads();

        // exp, write P to smem, partial row sums, rescale O
        #pragma unroll
        for (int i = 0; i < 8; i++) {
            const int r = row0 + i;
            const float mn = mrow[r];
            const float a  = arow[r];
            float rs = 0.f;
            #pragma unroll
            for (int j = 0; j < 4; j++) {
                float p = __expf(fmaf(sacc[i][j], sc, -mn));
                Ps[r * QP + col0 + j] = p;
                rs += p;
            }
            red[r * 17 + tx] = rs;
            #pragma unroll
            for (int j = 0; j < 4; j++) oacc[i][j] *= a;
        }
        __syncthreads();
        if (tid < BR) {
            float s0 = 0.f;
            #pragma unroll
            for (int c = 0; c < 16; c++) s0 += red[tid * 17 + c];
            lrow[tid] = lrow[tid] * arow[tid] + s0;
        }
        // no sync needed: O-gemm below touches only Ps (synced) and Vs

        // O += P V
        for (int k = 0; k < BC; k++) {
            float pv[8], vv[4];
            #pragma unroll
            for (int i = 0; i < 8; i++) pv[i] = Ps[(row0 + i) * QP + k];
            #pragma unroll
            for (int j = 0; j < 4; j++) vv[j] = Vs[k * QP + col0 + j];
            #pragma unroll
            for (int i = 0; i < 8; i++)
                #pragma unroll
                for (int j = 0; j < 4; j++)
                    oacc[i][j] = fmaf(pv[i], vv[j], oacc[i][j]);
        }
    }
    __syncthreads();                     // final lrow writes visible

    #pragma unroll
    for (int i = 0; i < 8; i++) {
        const int r = row0 + i;
        const float inv = 1.f / lrow[r];
        float4 o;
        o.x = oacc[i][0] * inv; o.y = oacc[i][1] * inv;
        o.z = oacc[i][2] * inv; o.w = oacc[i][3] * inv;
        *(float4*)(Og + base + (size_t)(qbase + r) * DIM + col0) = o;
    }
}

// ---------------- launcher ----------------
extern "C" void kernel_launch(void* const* d_in, const int* in_sizes, int n_in,
                              void* d_out, int out_size) {
    const float* query = (const float*)d_in[0];
    const float* key   = (const float*)d_in[1];
    const float* value = (const float*)d_in[2];
    const float* cond  = (const float*)d_in[3];
    const float* Wq = (const float*)d_in[4];
    const float* bq = (const float*)d_in[5];
    const float* Wk = (const float*)d_in[6];
    const float* bk = (const float*)d_in[7];
    const float* Wv = (const float*)d_in[8];
    const float* bv = (const float*)d_in[9];
    const float* Wo = (const float*)d_in[10];
    const float* bo = (const float*)d_in[11];
    const float* Wc1 = (const float*)d_in[12];
    const float* bc1 = (const float*)d_in[13];
    const float* Wc2 = (const float*)d_in[14];
    float* out = (float*)d_out;

    float *q, *k, *v, *x, *hb, *cb;
    cudaGetSymbolAddress((void**)&q,  g_q);
    cudaGetSymbolAddress((void**)&k,  g_k);
    cudaGetSymbolAddress((void**)&v,  g_v);
    cudaGetSymbolAddress((void**)&x,  g_x);
    cudaGetSymbolAddress((void**)&hb, g_h);
    cudaGetSymbolAddress((void**)&cb, g_c);

    cudaFuncSetAttribute(flash_attn, cudaFuncAttributeMaxDynamicSharedMemorySize,
                         FA_SMEM_BYTES);

    // cond MLP
    cond_mlp1<<<BATCH, HID>>>(cond, Wc1, bc1, hb);
    cond_mlp2<<<BATCH, DIM>>>(hb, Wc2, cb);

    // projections
    dim3 gg(DIM / GBN, MROWS / GBM);   // (8, 32)
    sgemm_bias<<<gg, 256>>>(query, Wq, bq, nullptr, q, MROWS, DIM, DIM, SEQ);
    sgemm_bias<<<gg, 256>>>(key,   Wk, bk, nullptr, k, MROWS, DIM, DIM, SEQ);
    sgemm_bias<<<gg, 256>>>(value, Wv, bv, cb,      v, MROWS, DIM, DIM, SEQ);

    // attention
    flash_attn<<<dim3(SEQ / BR, BATCH * HEADS), 256, FA_SMEM_BYTES>>>(q, k, v, x);

    // output projection
    sgemm_bias<<<gg, 256>>>(x, Wo, bo, nullptr, out, MROWS, DIM, DIM, SEQ);
}

// round 9
// speedup vs baseline: 1.0022x; 1.0007x over previous
#include <cuda_runtime.h>
#include <cuda_bf16.h>
#include <cstdint>

// Problem constants
#define BATCH 2
#define SEQ   2048
#define DIM   1024
#define HEADS 16
#define DK    64
#define CL    256
#define HID   512
#define MROWS (BATCH*SEQ)   // 4096

// ---------------- scratch (device globals; no allocation allowed) ----------------
__device__ float g_q[MROWS * DIM];
__device__ float g_k[MROWS * DIM];
__device__ float g_v[MROWS * DIM];
__device__ float g_x[MROWS * DIM];
__device__ float g_h[BATCH * HID];
__device__ float g_c[BATCH * DIM];

// ---------------- cond MLP ----------------
// h[b][j] = relu(sum_k cond[b][k] * Wc1[k][j] + bc1[j])
__global__ void cond_mlp1(const float* __restrict__ cond, const float* __restrict__ Wc1,
                          const float* __restrict__ bc1, float* __restrict__ h) {
    int b = blockIdx.x;
    int j = threadIdx.x;            // 512
    float acc = bc1[j];
    const float* cr = cond + b * CL;
    #pragma unroll 8
    for (int k = 0; k < CL; k++) acc = fmaf(cr[k], Wc1[k * HID + j], acc);
    h[b * HID + j] = acc > 0.f ? acc : 0.f;
}

// c[b][n] = sum_k h[b][k] * Wc2[k][n]
__global__ void cond_mlp2(const float* __restrict__ h, const float* __restrict__ Wc2,
                          float* __restrict__ c) {
    int b = blockIdx.x;
    int n = threadIdx.x;            // 1024
    float acc = 0.f;
    const float* hr = h + b * HID;
    #pragma unroll 8
    for (int k = 0; k < HID; k++) acc = fmaf(hr[k], Wc2[k * DIM + n], acc);
    c[b * DIM + n] = acc;
}

// ---------------- fp32 SGEMM: C[M,N] = A[M,K] @ W[K,N] + bias[n] (+ cb[row/S][n]) ----
#define GBM 128
#define GBN 128
#define GBK 8

__global__ __launch_bounds__(256, 2)
void sgemm_bias(const float* __restrict__ A, const float* __restrict__ W,
                const float* __restrict__ bias, const float* __restrict__ cb,
                float* __restrict__ C, int M, int N, int K, int S) {
    __shared__ float As[GBK][GBM + 4];   // [k][m], padded
    __shared__ float Bs[GBK][GBN];       // [k][n]

    const int tid  = threadIdx.x;        // 256
    const int trow = tid >> 4;           // 0..15
    const int tcol = tid & 15;           // 0..15
    const int bm = blockIdx.y * GBM;
    const int bn = blockIdx.x * GBN;

    const int arow = tid >> 1;           // 0..127
    const int acol = (tid & 1) << 2;     // 0 or 4
    const int brow = tid >> 5;           // 0..7
    const int bcol = (tid & 31) << 2;    // 0..124

    float acc[8][8];
    #pragma unroll
    for (int i = 0; i < 8; i++)
        #pragma unroll
        for (int j = 0; j < 8; j++) acc[i][j] = 0.f;

    for (int k0 = 0; k0 < K; k0 += GBK) {
        float4 av = *(const float4*)(A + (size_t)(bm + arow) * K + k0 + acol);
        As[acol + 0][arow] = av.x;
        As[acol + 1][arow] = av.y;
        As[acol + 2][arow] = av.z;
        As[acol + 3][arow] = av.w;
        float4 bv = *(const float4*)(W + (size_t)(k0 + brow) * N + bn + bcol);
        *(float4*)&Bs[brow][bcol] = bv;
        __syncthreads();

        #pragma unroll
        for (int k = 0; k < GBK; k++) {
            float ra[8], rb[8];
            #pragma unroll
            for (int i = 0; i < 8; i++) ra[i] = As[k][trow * 8 + i];
            #pragma unroll
            for (int j = 0; j < 8; j++) rb[j] = Bs[k][tcol * 8 + j];
            #pragma unroll
            for (int i = 0; i < 8; i++)
                #pragma unroll
                for (int j = 0; j < 8; j++)
                    acc[i][j] = fmaf(ra[i], rb[j], acc[i][j]);
        }
        __syncthreads();
    }

    #pragma unroll
    for (int i = 0; i < 8; i++) {
        const int row = bm + trow * 8 + i;
        const int batch = row / S;
        const float* cbr = cb ? (cb + (size_t)batch * N) : nullptr;
        #pragma unroll
        for (int j = 0; j < 8; j += 4) {
            const int col = bn + tcol * 8 + j;
            float4 o;
            o.x = acc[i][j + 0] + bias[col + 0];
            o.y = acc[i][j + 1] + bias[col + 1];
            o.z = acc[i][j + 2] + bias[col + 2];
            o.w = acc[i][j + 3] + bias[col + 3];
            if (cbr) {
                o.x += cbr[col + 0]; o.y += cbr[col + 1];
                o.z += cbr[col + 2]; o.w += cbr[col + 3];
            }
            *(float4*)(C + (size_t)row * N + col) = o;
        }
    }
}

// ---------------- flash attention (fp32, online softmax) ----------------
// Br=128 query rows per CTA, Bc=64 key rows per iteration, dk=64.
// 256 threads: ty=tid/16 owns 8 q-rows, tx=tid%16 owns 4 cols.
#define BR 128
#define BC 64
#define QP 65                    // smem pitch (floats)
#define FA_SMEM_FLOATS (BR*QP /*Q*/ + BC*QP /*K*/ + BC*QP /*V*/ + BR*QP /*P*/ + BR*17 /*red*/ + 3*BR)
#define FA_SMEM_BYTES  (FA_SMEM_FLOATS * 4)

__global__ __launch_bounds__(256, 2)
void flash_attn(const float* __restrict__ Qg, const float* __restrict__ Kg,
                const float* __restrict__ Vg, float* __restrict__ Og) {
    extern __shared__ float sm[];
    float* Qs   = sm;                    // [BR][QP]
    float* Ks   = Qs + BR * QP;          // [BC][QP]
    float* Vs   = Ks + BC * QP;          // [BC][QP]
    float* Ps   = Vs + BC * QP;          // [BR][QP]
    float* red  = Ps + BR * QP;          // [BR][17]
    float* mrow = red + BR * 17;         // [BR]
    float* lrow = mrow + BR;             // [BR]
    float* arow = lrow + BR;             // [BR]

    const int tid = threadIdx.x;
    const int ty = tid >> 4;             // 0..15
    const int tx = tid & 15;             // 0..15
    const int row0 = ty * 8;
    const int col0 = tx * 4;

    const int qb = blockIdx.x;           // 0..15
    const int bh = blockIdx.y;           // 0..31
    const int b = bh >> 4, h = bh & 15;
    const size_t base = (size_t)b * SEQ * DIM + h * DK;
    const int qbase = qb * BR;

    // load Q tile [BR x DK]
    #pragma unroll
    for (int i = 0; i < 8; i++) {
        int idx = tid + i * 256;         // 0..2047
        int r = idx >> 4;
        int c4 = (idx & 15) << 2;
        float4 v = *(const float4*)(Qg + base + (size_t)(qbase + r) * DIM + c4);
        float* d = Qs + r * QP + c4;
        d[0] = v.x; d[1] = v.y; d[2] = v.z; d[3] = v.w;
    }
    if (tid < BR) { mrow[tid] = -1e30f; lrow[tid] = 0.f; }

    float oacc[8][4];
    #pragma unroll
    for (int i = 0; i < 8; i++)
        #pragma unroll
        for (int j = 0; j < 4; j++) oacc[i][j] = 0.f;

    const float sc = 0.125f;             // 1/sqrt(64)

    for (int kb = 0; kb < SEQ / BC; kb++) {
        __syncthreads();                 // protect Ks/Vs reuse, cover first-iter Qs
        const int kbase = kb * BC;
        #pragma unroll
        for (int i = 0; i < 4; i++) {
            int idx = tid + i * 256;     // 0..1023
            int r = idx >> 4;
            int c4 = (idx & 15) << 2;
            float4 kv = *(const float4*)(Kg + base + (size_t)(kbase + r) * DIM + c4);
            float* kd = Ks + r * QP + c4;
            kd[0] = kv.x; kd[1] = kv.y; kd[2] = kv.z; kd[3] = kv.w;
            float4 vv = *(const float4*)(Vg + base + (size_t)(kbase + r) * DIM + c4);
            float* vd = Vs + r * QP + c4;
            vd[0] = vv.x; vd[1] = vv.y; vd[2] = vv.z; vd[3] = vv.w;
        }
        __syncthreads();

        // S = Q K^T (scaled later)
        float sacc[8][4];
        #pragma unroll
        for (int i = 0; i < 8; i++)
            #pragma unroll
            for (int j = 0; j < 4; j++) sacc[i][j] = 0.f;

        for (int d = 0; d < DK; d++) {
            float qv[8], kv[4];
            #pragma unroll
            for (int i = 0; i < 8; i++) qv[i] = Qs[(row0 + i) * QP + d];
            #pragma unroll
            for (int j = 0; j < 4; j++) kv[j] = Ks[(col0 + j) * QP + d];
            #pragma unroll
            for (int i = 0; i < 8; i++)
                #pragma unroll
                for (int j = 0; j < 4; j++)
                    sacc[i][j] = fmaf(qv[i], kv[j], sacc[i][j]);
        }

        // partial row max (of scaled scores)
        #pragma unroll
        for (int i = 0; i < 8; i++) {
            float mx = fmaxf(fmaxf(sacc[i][0], sacc[i][1]),
                             fmaxf(sacc[i][2], sacc[i][3]));
            red[(row0 + i) * 17 + tx] = mx * sc;
        }
        __syncthreads();
        if (tid < BR) {
            float mx = red[tid * 17];
            #pragma unroll
            for (int c = 1; c < 16; c++) mx = fmaxf(mx, red[tid * 17 + c]);
            float mold = mrow[tid];
            float mnew = fmaxf(mold, mx);
            mrow[tid] = mnew;
            arow[tid] = __expf(mold - mnew);
        }
        __syncthreads();

        // exp, write P to smem, partial row sums, rescale O
        #pragma unroll
        for (int i = 0; i < 8; i++) {
            const int r = row0 + i;
            const float mn = mrow[r];
            const float a  = arow[r];
            float rs = 0.f;
            #pragma unroll
            for (int j = 0; j < 4; j++) {
                float p = __expf(fmaf(sacc[i][j], sc, -mn));
                Ps[r * QP + col0 + j] = p;
                rs += p;
            }
            red[r * 17 + tx] = rs;
            #pragma unroll
            for (int j = 0; j < 4; j++) oacc[i][j] *= a;
        }
        __syncthreads();
        if (tid < BR) {
            float s0 = 0.f;
            #pragma unroll
            for (int c = 0; c < 16; c++) s0 += red[tid * 17 + c];
            lrow[tid] = lrow[tid] * arow[tid] + s0;
        }
        // no sync needed: O-gemm below touches only Ps (synced) and Vs

        // O += P V
        for (int k = 0; k < BC; k++) {
            float pv[8], vv[4];
            #pragma unroll
            for (int i = 0; i < 8; i++) pv[i] = Ps[(row0 + i) * QP + k];
            #pragma unroll
            for (int j = 0; j < 4; j++) vv[j] = Vs[k * QP + col0 + j];
            #pragma unroll
            for (int i = 0; i < 8; i++)
                #pragma unroll
                for (int j = 0; j < 4; j++)
                    oacc[i][j] = fmaf(pv[i], vv[j], oacc[i][j]);
        }
    }
    __syncthreads();                     // final lrow writes visible

    #pragma unroll
    for (int i = 0; i < 8; i++) {
        const int r = row0 + i;
        const float inv = 1.f / lrow[r];
        float4 o;
        o.x = oacc[i][0] * inv; o.y = oacc[i][1] * inv;
        o.z = oacc[i][2] * inv; o.w = oacc[i][3] * inv;
        *(float4*)(Og + base + (size_t)(qbase + r) * DIM + col0) = o;
    }
}

// ---------------- launcher ----------------
extern "C" void kernel_launch(void* const* d_in, const int* in_sizes, int n_in,
                              void* d_out, int out_size) {
    const float* query = (const float*)d_in[0];
    const float* key   = (const float*)d_in[1];
    const float* value = (const float*)d_in[2];
    const float* cond  = (const float*)d_in[3];
    const float* Wq = (const float*)d_in[4];
    const float* bq = (const float*)d_in[5];
    const float* Wk = (const float*)d_in[6];
    const float* bk = (const float*)d_in[7];
    const float* Wv = (const float*)d_in[8];
    const float* bv = (const float*)d_in[9];
    const float* Wo = (const float*)d_in[10];
    const float* bo = (const float*)d_in[11];
    const float* Wc1 = (const float*)d_in[12];
    const float* bc1 = (const float*)d_in[13];
    const float* Wc2 = (const float*)d_in[14];
    float* out = (float*)d_out;

    float *q, *k, *v, *x, *hb, *cb;
    cudaGetSymbolAddress((void**)&q,  g_q);
    cudaGetSymbolAddress((void**)&k,  g_k);
    cudaGetSymbolAddress((void**)&v,  g_v);
    cudaGetSymbolAddress((void**)&x,  g_x);
    cudaGetSymbolAddress((void**)&hb, g_h);
    cudaGetSymbolAddress((void**)&cb, g_c);

    cudaFuncSetAttribute(flash_attn, cudaFuncAttributeMaxDynamicSharedMemorySize,
                         FA_SMEM_BYTES);

    // cond MLP
    cond_mlp1<<<BATCH, HID>>>(cond, Wc1, bc1, hb);
    cond_mlp2<<<BATCH, DIM>>>(hb, Wc2, cb);

    // projections
    dim3 gg(DIM / GBN, MROWS / GBM);   // (8, 32)
    sgemm_bias<<<gg, 256>>>(query, Wq, bq, nullptr, q, MROWS, DIM, DIM, SEQ);
    sgemm_bias<<<gg, 256>>>(key,   Wk, bk, nullptr, k, MROWS, DIM, DIM, SEQ);
    sgemm_bias<<<gg, 256>>>(value, Wv, bv, cb,      v, MROWS, DIM, DIM, SEQ);

    // attention
    flash_attn<<<dim3(SEQ / BR, BATCH * HEADS), 256, FA_SMEM_BYTES>>>(q, k, v, x);

    // output projection
    sgemm_bias<<<gg, 256>>>(x, Wo, bo, nullptr, out, MROWS, DIM, DIM, SEQ);
}

// round 11
// speedup vs baseline: 1.3629x; 1.3600x over previous
#include <cuda_runtime.h>
#include <cuda_bf16.h>
#include <cstdint>

// Problem constants
#define BATCH 2
#define SEQ   2048
#define DIM   1024
#define HEADS 16
#define DK    64
#define CL    256
#define HID   512
#define MROWS (BATCH*SEQ)   // 4096

// ---------------- scratch (device globals; no allocation allowed) ----------------
__device__ float g_q[MROWS * DIM];
__device__ float g_k[MROWS * DIM];
__device__ float g_v[MROWS * DIM];
__device__ float g_x[MROWS * DIM];
__device__ float g_h[BATCH * HID];
__device__ float g_c[BATCH * DIM];
__device__ __nv_bfloat16 g_ahi[MROWS * DIM];
__device__ __nv_bfloat16 g_alo[MROWS * DIM];
__device__ __nv_bfloat16 g_whi[DIM * DIM];   // transposed: [N][K]
__device__ __nv_bfloat16 g_wlo[DIM * DIM];   // transposed: [N][K]

// ================= PTX helpers (baseline PTX only — no tcgen05!) =================
__device__ __forceinline__ uint32_t smem_u32(const void* p) {
    uint32_t a;
    asm("{ .reg .u64 t; cvta.to.shared.u64 t, %1; cvt.u32.u64 %0, t; }" : "=r"(a) : "l"(p));
    return a;
}
__device__ __forceinline__ void cp_async16(uint32_t dst, const void* src) {
    asm volatile("cp.async.cg.shared.global [%0], [%1], 16;" :: "r"(dst), "l"(src) : "memory");
}
__device__ __forceinline__ void cp_commit() {
    asm volatile("cp.async.commit_group;" ::: "memory");
}
__device__ __forceinline__ void ldsm_x4(uint32_t* r, uint32_t addr) {
    asm volatile("ldmatrix.sync.aligned.m8n8.x4.shared.b16 {%0,%1,%2,%3}, [%4];"
                 : "=r"(r[0]), "=r"(r[1]), "=r"(r[2]), "=r"(r[3]) : "r"(addr));
}
__device__ __forceinline__ void mma_bf16(float* d, const uint32_t* a, uint32_t b0, uint32_t b1) {
    asm volatile(
        "mma.sync.aligned.m16n8k16.row.col.f32.bf16.bf16.f32 "
        "{%0,%1,%2,%3}, {%4,%5,%6,%7}, {%8,%9}, {%0,%1,%2,%3};"
        : "+f"(d[0]), "+f"(d[1]), "+f"(d[2]), "+f"(d[3])
        : "r"(a[0]), "r"(a[1]), "r"(a[2]), "r"(a[3]), "r"(b0), "r"(b1));
}

// ---------------- split conversions ----------------
__global__ void split_f32(const float4* __restrict__ x, __nv_bfloat16* __restrict__ hi,
                          __nv_bfloat16* __restrict__ lo, int n4) {
    int i = blockIdx.x * blockDim.x + threadIdx.x;
    if (i >= n4) return;
    float4 v = x[i];
    __nv_bfloat16 h0 = __float2bfloat16(v.x), h1 = __float2bfloat16(v.y);
    __nv_bfloat16 h2 = __float2bfloat16(v.z), h3 = __float2bfloat16(v.w);
    __nv_bfloat16 l0 = __float2bfloat16(v.x - __bfloat162float(h0));
    __nv_bfloat16 l1 = __float2bfloat16(v.y - __bfloat162float(h1));
    __nv_bfloat16 l2 = __float2bfloat16(v.z - __bfloat162float(h2));
    __nv_bfloat16 l3 = __float2bfloat16(v.w - __bfloat162float(h3));
    ((__nv_bfloat162*)hi)[2 * i]     = __nv_bfloat162(h0, h1);
    ((__nv_bfloat162*)hi)[2 * i + 1] = __nv_bfloat162(h2, h3);
    ((__nv_bfloat162*)lo)[2 * i]     = __nv_bfloat162(l0, l1);
    ((__nv_bfloat162*)lo)[2 * i + 1] = __nv_bfloat162(l2, l3);
}

// W [K,N] -> W^T split: hiT/loT [N][K]
__global__ void split_w_T(const float* __restrict__ W, __nv_bfloat16* __restrict__ hiT,
                          __nv_bfloat16* __restrict__ loT) {
    __shared__ float t[32][33];
    int n0 = blockIdx.x * 32, k0 = blockIdx.y * 32;
    int tx = threadIdx.x, ty = threadIdx.y;   // 32 x 8
    #pragma unroll
    for (int i = ty; i < 32; i += 8) t[i][tx] = W[(size_t)(k0 + i) * DIM + n0 + tx];
    __syncthreads();
    #pragma unroll
    for (int i = ty; i < 32; i += 8) {
        float v = t[tx][i];                   // = W[k0+tx][n0+i]
        __nv_bfloat16 h = __float2bfloat16(v);
        __nv_bfloat16 l = __float2bfloat16(v - __bfloat162float(h));
        hiT[(size_t)(n0 + i) * DIM + k0 + tx] = h;
        loT[(size_t)(n0 + i) * DIM + k0 + tx] = l;
    }
}

// ---------------- cond MLP ----------------
__global__ void cond_mlp1(const float* __restrict__ cond, const float* __restrict__ Wc1,
                          const float* __restrict__ bc1, float* __restrict__ h) {
    int b = blockIdx.x;
    int j = threadIdx.x;
    float acc = bc1[j];
    const float* cr = cond + b * CL;
    #pragma unroll 8
    for (int k = 0; k < CL; k++) acc = fmaf(cr[k], Wc1[k * HID + j], acc);
    h[b * HID + j] = acc > 0.f ? acc : 0.f;
}
__global__ void cond_mlp2(const float* __restrict__ h, const float* __restrict__ Wc2,
                          float* __restrict__ c) {
    int b = blockIdx.x;
    int n = threadIdx.x;
    float acc = 0.f;
    const float* hr = h + b * HID;
    #pragma unroll 8
    for (int k = 0; k < HID; k++) acc = fmaf(hr[k], Wc2[k * DIM + n], acc);
    c[b * DIM + n] = acc;
}

// ---------------- mma.sync split-bf16 GEMM ----------------
// C[M,N] = A[M,K] @ W[K,N] + bias[n] (+ cb[row/S][n])
// A split bf16 [M][K]; W^T split bf16 [N][K]. CTA tile 128x128, K chunk 64,
// 2-stage cp.async double buffer, 256 threads = 8 warps (4 along M x 2 along N).
#define KC 64
#define NCHUNK (DIM / KC)                // 16
#define TPITCH 144                       // bytes per smem row (72 bf16) — 16B aligned, conflict-free
#define TILE_BYTES (128 * TPITCH)        // 18432
#define STAGE_BYTES (4 * TILE_BYTES)     // Ahi, Alo, Bhi, Blo = 73728
#define GEMM_SMEM (2 * STAGE_BYTES)      // 147456

__device__ __forceinline__ void load_chunk(uint32_t stg, const __nv_bfloat16* Ahi,
                                           const __nv_bfloat16* Alo, const __nv_bfloat16* BhiT,
                                           const __nv_bfloat16* BloT, int bm, int bn, int k0, int tid) {
    #pragma unroll
    for (int i = 0; i < 4; i++) {
        int idx = tid + i * 256;             // 0..1023
        int r = idx >> 3;                    // row 0..127
        int c = (idx & 7) << 4;              // byte col 0..112
        uint32_t dst = (uint32_t)(r * TPITCH + c);
        cp_async16(stg + 0 * TILE_BYTES + dst, (const char*)(Ahi  + (size_t)(bm + r) * DIM + k0) + c);
        cp_async16(stg + 1 * TILE_BYTES + dst, (const char*)(Alo  + (size_t)(bm + r) * DIM + k0) + c);
        cp_async16(stg + 2 * TILE_BYTES + dst, (const char*)(BhiT + (size_t)(bn + r) * DIM + k0) + c);
        cp_async16(stg + 3 * TILE_BYTES + dst, (const char*)(BloT + (size_t)(bn + r) * DIM + k0) + c);
    }
    cp_commit();
}

__global__ __launch_bounds__(256, 1)
void gemm_mma(const __nv_bfloat16* __restrict__ Ahi, const __nv_bfloat16* __restrict__ Alo,
              const __nv_bfloat16* __restrict__ BhiT, const __nv_bfloat16* __restrict__ BloT,
              const float* __restrict__ bias, const float* __restrict__ cb,
              float* __restrict__ C, int S) {
    extern __shared__ char smem[];
    uint32_t sbase = smem_u32(smem);
    const int tid = threadIdx.x;
    const int lane = tid & 31, wid = tid >> 5;
    const int wm = wid & 3;                  // 0..3  -> M offset wm*32
    const int wn = wid >> 2;                 // 0..1  -> N offset wn*64
    const int bm = blockIdx.y * 128, bn = blockIdx.x * 128;

    float acc[2][8][4];
    #pragma unroll
    for (int mb = 0; mb < 2; mb++)
        #pragma unroll
        for (int j = 0; j < 8; j++)
            #pragma unroll
            for (int r = 0; r < 4; r++) acc[mb][j][r] = 0.f;

    // ldmatrix lane address components
    const int alr = lane & 15, alh = lane >> 4;               // A: rows, k-half
    const int bnr = (lane & 7) + (lane >> 4) * 8;             // B: n rows
    const int bkh = (lane >> 3) & 1;                          // B: k-half

    load_chunk(sbase,               Ahi, Alo, BhiT, BloT, bm, bn, 0,  tid);
    load_chunk(sbase + STAGE_BYTES, Ahi, Alo, BhiT, BloT, bm, bn, KC, tid);

    for (int i = 0; i < NCHUNK; i++) {
        if (i == NCHUNK - 1) asm volatile("cp.async.wait_group 0;" ::: "memory");
        else                 asm volatile("cp.async.wait_group 1;" ::: "memory");
        __syncthreads();

        const uint32_t stg   = sbase + (uint32_t)(i & 1) * STAGE_BYTES;
        const uint32_t ahi_b = stg + wm * 32 * TPITCH;
        const uint32_t bhi_b = stg + 2 * TILE_BYTES + wn * 64 * TPITCH;

        #pragma unroll
        for (int kb = 0; kb < 4; kb++) {
            const uint32_t koff = kb * 32;
            uint32_t ah[2][4], al[2][4];
            #pragma unroll
            for (int mb = 0; mb < 2; mb++) {
                uint32_t aaddr = ahi_b + (uint32_t)((mb * 16 + alr) * TPITCH) + koff + alh * 16;
                ldsm_x4(ah[mb], aaddr);
                ldsm_x4(al[mb], aaddr + TILE_BYTES);
            }
            uint32_t bh[4][4], bl[4][4];
            #pragma unroll
            for (int g = 0; g < 4; g++) {
                uint32_t baddr = bhi_b + (uint32_t)((g * 16 + bnr) * TPITCH) + koff + bkh * 16;
                ldsm_x4(bh[g], baddr);
                ldsm_x4(bl[g], baddr + TILE_BYTES);
            }
            #pragma unroll
            for (int mb = 0; mb < 2; mb++)
                #pragma unroll
                for (int g = 0; g < 4; g++)
                    #pragma unroll
                    for (int h = 0; h < 2; h++) {
                        float* d = acc[mb][g * 2 + h];
                        mma_bf16(d, ah[mb], bh[g][2 * h], bh[g][2 * h + 1]);  // hi*hi
                        mma_bf16(d, ah[mb], bl[g][2 * h], bl[g][2 * h + 1]);  // hi*lo
                        mma_bf16(d, al[mb], bh[g][2 * h], bh[g][2 * h + 1]);  // lo*hi
                    }
        }
        __syncthreads();
        if (i + 2 < NCHUNK)
            load_chunk(stg, Ahi, Alo, BhiT, BloT, bm, bn, (i + 2) * KC, tid);
    }

    // epilogue
    const int qr = lane >> 2, qc = lane & 3;
    const int batch = bm / S;
    const float* cbr = cb ? (cb + (size_t)batch * DIM) : nullptr;
    #pragma unroll
    for (int mb = 0; mb < 2; mb++) {
        const int row0 = bm + wm * 32 + mb * 16 + qr;
        #pragma unroll
        for (int j = 0; j < 8; j++) {
            const int col = bn + wn * 64 + j * 8 + qc * 2;
            float b0 = bias[col], b1 = bias[col + 1];
            if (cbr) { b0 += cbr[col]; b1 += cbr[col + 1]; }
            float2 v0 = make_float2(acc[mb][j][0] + b0, acc[mb][j][1] + b1);
            float2 v1 = make_float2(acc[mb][j][2] + b0, acc[mb][j][3] + b1);
            *(float2*)(C + (size_t)row0 * DIM + col)       = v0;
            *(float2*)(C + (size_t)(row0 + 8) * DIM + col) = v1;
        }
    }
}

// ---------------- flash attention (fp32, online softmax) — unchanged, verified ----------------
#define BR 128
#define BC 64
#define QP 65
#define FA_SMEM_FLOATS (BR*QP + BC*QP + BC*QP + BR*QP + BR*17 + 3*BR)
#define FA_SMEM_BYTES  (FA_SMEM_FLOATS * 4)

__global__ __launch_bounds__(256, 2)
void flash_attn(const float* __restrict__ Qg, const float* __restrict__ Kg,
                const float* __restrict__ Vg, float* __restrict__ Og) {
    extern __shared__ float sm[];
    float* Qs   = sm;
    float* Ks   = Qs + BR * QP;
    float* Vs   = Ks + BC * QP;
    float* Ps   = Vs + BC * QP;
    float* red  = Ps + BR * QP;
    float* mrow = red + BR * 17;
    float* lrow = mrow + BR;
    float* arow = lrow + BR;

    const int tid = threadIdx.x;
    const int ty = tid >> 4;
    const int tx = tid & 15;
    const int row0 = ty * 8;
    const int col0 = tx * 4;

    const int qb = blockIdx.x;
    const int bh = blockIdx.y;
    const int b = bh >> 4, h = bh & 15;
    const size_t base = (size_t)b * SEQ * DIM + h * DK;
    const int qbase = qb * BR;

    #pragma unroll
    for (int i = 0; i < 8; i++) {
        int idx = tid + i * 256;
        int r = idx >> 4;
        int c4 = (idx & 15) << 2;
        float4 v = *(const float4*)(Qg + base + (size_t)(qbase + r) * DIM + c4);
        float* d = Qs + r * QP + c4;
        d[0] = v.x; d[1] = v.y; d[2] = v.z; d[3] = v.w;
    }
    if (tid < BR) { mrow[tid] = -1e30f; lrow[tid] = 0.f; }

    float oacc[8][4];
    #pragma unroll
    for (int i = 0; i < 8; i++)
        #pragma unroll
        for (int j = 0; j < 4; j++) oacc[i][j] = 0.f;

    const float sc = 0.125f;

    for (int kb = 0; kb < SEQ / BC; kb++) {
        __syncthreads();
        const int kbase = kb * BC;
        #pragma unroll
        for (int i = 0; i < 4; i++) {
            int idx = tid + i * 256;
            int r = idx >> 4;
            int c4 = (idx & 15) << 2;
            float4 kv = *(const float4*)(Kg + base + (size_t)(kbase + r) * DIM + c4);
            float* kd = Ks + r * QP + c4;
            kd[0] = kv.x; kd[1] = kv.y; kd[2] = kv.z; kd[3] = kv.w;
            float4 vv = *(const float4*)(Vg + base + (size_t)(kbase + r) * DIM + c4);
            float* vd = Vs + r * QP + c4;
            vd[0] = vv.x; vd[1] = vv.y; vd[2] = vv.z; vd[3] = vv.w;
        }
        __syncthreads();

        float sacc[8][4];
        #pragma unroll
        for (int i = 0; i < 8; i++)
            #pragma unroll
            for (int j = 0; j < 4; j++) sacc[i][j] = 0.f;

        for (int d = 0; d < DK; d++) {
            float qv[8], kv[4];
            #pragma unroll
            for (int i = 0; i < 8; i++) qv[i] = Qs[(row0 + i) * QP + d];
            #pragma unroll
            for (int j = 0; j < 4; j++) kv[j] = Ks[(col0 + j) * QP + d];
            #pragma unroll
            for (int i = 0; i < 8; i++)
                #pragma unroll
                for (int j = 0; j < 4; j++)
                    sacc[i][j] = fmaf(qv[i], kv[j], sacc[i][j]);
        }

        #pragma unroll
        for (int i = 0; i < 8; i++) {
            float mx = fmaxf(fmaxf(sacc[i][0], sacc[i][1]),
                             fmaxf(sacc[i][2], sacc[i][3]));
            red[(row0 + i) * 17 + tx] = mx * sc;
        }
        __syncthreads();
        if (tid < BR) {
            float mx = red[tid * 17];
            #pragma unroll
            for (int c = 1; c < 16; c++) mx = fmaxf(mx, red[tid * 17 + c]);
            float mold = mrow[tid];
            float mnew = fmaxf(mold, mx);
            mrow[tid] = mnew;
            arow[tid] = __expf(mold - mnew);
        }
        __syncthreads();

        #pragma unroll
        for (int i = 0; i < 8; i++) {
            const int r = row0 + i;
            const float mn = mrow[r];
            const float a  = arow[r];
            float rs = 0.f;
            #pragma unroll
            for (int j = 0; j < 4; j++) {
                float p = __expf(fmaf(sacc[i][j], sc, -mn));
                Ps[r * QP + col0 + j] = p;
                rs += p;
            }
            red[r * 17 + tx] = rs;
            #pragma unroll
            for (int j = 0; j < 4; j++) oacc[i][j] *= a;
        }
        __syncthreads();
        if (tid < BR) {
            float s0 = 0.f;
            #pragma unroll
            for (int c = 0; c < 16; c++) s0 += red[tid * 17 + c];
            lrow[tid] = lrow[tid] * arow[tid] + s0;
        }

        for (int k = 0; k < BC; k++) {
            float pv[8], vv[4];
            #pragma unroll
            for (int i = 0; i < 8; i++) pv[i] = Ps[(row0 + i) * QP + k];
            #pragma unroll
            for (int j = 0; j < 4; j++) vv[j] = Vs[k * QP + col0 + j];
            #pragma unroll
            for (int i = 0; i < 8; i++)
                #pragma unroll
                for (int j = 0; j < 4; j++)
                    oacc[i][j] = fmaf(pv[i], vv[j], oacc[i][j]);
        }
    }
    __syncthreads();

    #pragma unroll
    for (int i = 0; i < 8; i++) {
        const int r = row0 + i;
        const float inv = 1.f / lrow[r];
        float4 o;
        o.x = oacc[i][0] * inv; o.y = oacc[i][1] * inv;
        o.z = oacc[i][2] * inv; o.w = oacc[i][3] * inv;
        *(float4*)(Og + base + (size_t)(qbase + r) * DIM + col0) = o;
    }
}

// ---------------- launcher ----------------
extern "C" void kernel_launch(void* const* d_in, const int* in_sizes, int n_in,
                              void* d_out, int out_size) {
    const float* query = (const float*)d_in[0];
    const float* key   = (const float*)d_in[1];
    const float* value = (const float*)d_in[2];
    const float* cond  = (const float*)d_in[3];
    const float* Wq = (const float*)d_in[4];
    const float* bq = (const float*)d_in[5];
    const float* Wk = (const float*)d_in[6];
    const float* bk = (const float*)d_in[7];
    const float* Wv = (const float*)d_in[8];
    const float* bv = (const float*)d_in[9];
    const float* Wo = (const float*)d_in[10];
    const float* bo = (const float*)d_in[11];
    const float* Wc1 = (const float*)d_in[12];
    const float* bc1 = (const float*)d_in[13];
    const float* Wc2 = (const float*)d_in[14];
    float* out = (float*)d_out;

    float *q, *k, *v, *x, *hb, *cb;
    __nv_bfloat16 *ahi, *alo, *whi, *wlo;
    cudaGetSymbolAddress((void**)&q,  g_q);
    cudaGetSymbolAddress((void**)&k,  g_k);
    cudaGetSymbolAddress((void**)&v,  g_v);
    cudaGetSymbolAddress((void**)&x,  g_x);
    cudaGetSymbolAddress((void**)&hb, g_h);
    cudaGetSymbolAddress((void**)&cb, g_c);
    cudaGetSymbolAddress((void**)&ahi, g_ahi);
    cudaGetSymbolAddress((void**)&alo, g_alo);
    cudaGetSymbolAddress((void**)&whi, g_whi);
    cudaGetSymbolAddress((void**)&wlo, g_wlo);

    cudaFuncSetAttribute(flash_attn, cudaFuncAttributeMaxDynamicSharedMemorySize, FA_SMEM_BYTES);
    cudaFuncSetAttribute(gemm_mma, cudaFuncAttributeMaxDynamicSharedMemorySize, GEMM_SMEM);

    const int n4 = MROWS * DIM / 4;
    dim3 tgrid(DIM / 32, DIM / 32), tblk(32, 8);
    dim3 ggrid(DIM / 128, MROWS / 128);               // (8, 32)

    // cond MLP -> cb
    cond_mlp1<<<BATCH, HID>>>(cond, Wc1, bc1, hb);
    cond_mlp2<<<BATCH, DIM>>>(hb, Wc2, cb);

    // Q projection
    split_w_T<<<tgrid, tblk>>>(Wq, whi, wlo);
    split_f32<<<n4 / 256, 256>>>((const float4*)query, ahi, alo, n4);
    gemm_mma<<<ggrid, 256, GEMM_SMEM>>>(ahi, alo, whi, wlo, bq, nullptr, q, SEQ);

    // K projection
    split_w_T<<<tgrid, tblk>>>(Wk, whi, wlo);
    split_f32<<<n4 / 256, 256>>>((const float4*)key, ahi, alo, n4);
    gemm_mma<<<ggrid, 256, GEMM_SMEM>>>(ahi, alo, whi, wlo, bk, nullptr, k, SEQ);

    // V projection (+ cond bias)
    split_w_T<<<tgrid, tblk>>>(Wv, whi, wlo);
    split_f32<<<n4 / 256, 256>>>((const float4*)value, ahi, alo, n4);
    gemm_mma<<<ggrid, 256, GEMM_SMEM>>>(ahi, alo, whi, wlo, bv, cb, v, SEQ);

    // attention
    flash_attn<<<dim3(SEQ / BR, BATCH * HEADS), 256, FA_SMEM_BYTES>>>(q, k, v, x);

    // output projection
    split_w_T<<<tgrid, tblk>>>(Wo, whi, wlo);
    split_f32<<<n4 / 256, 256>>>((const float4*)x, ahi, alo, n4);
    gemm_mma<<<ggrid, 256, GEMM_SMEM>>>(ahi, alo, whi, wlo, bo, nullptr, out, SEQ);
}

// round 12
// speedup vs baseline: 2.7766x; 2.0372x over previous
#include <cuda_runtime.h>
#include <cuda_bf16.h>
#include <cstdint>

// Problem constants
#define BATCH 2
#define SEQ   2048
#define DIM   1024
#define HEADS 16
#define DK    64
#define CL    256
#define HID   512
#define MROWS (BATCH*SEQ)   // 4096

// ---------------- scratch (device globals; no allocation allowed) ----------------
__device__ float g_h[BATCH * HID];
__device__ float g_c[BATCH * DIM];
__device__ __nv_bfloat16 g_ahi[MROWS * DIM];
__device__ __nv_bfloat16 g_alo[MROWS * DIM];
__device__ __nv_bfloat16 g_whi[DIM * DIM];   // transposed: [N][K]
__device__ __nv_bfloat16 g_wlo[DIM * DIM];
__device__ __nv_bfloat16 g_qhi[MROWS * DIM];
__device__ __nv_bfloat16 g_qlo[MROWS * DIM];
__device__ __nv_bfloat16 g_khi[MROWS * DIM];
__device__ __nv_bfloat16 g_klo[MROWS * DIM];
__device__ __nv_bfloat16 g_vhi[MROWS * DIM];
__device__ __nv_bfloat16 g_vlo[MROWS * DIM];
__device__ __nv_bfloat16 g_xhi[MROWS * DIM];
__device__ __nv_bfloat16 g_xlo[MROWS * DIM];

// ================= PTX helpers (baseline PTX only) =================
__device__ __forceinline__ uint32_t smem_u32(const void* p) {
    uint32_t a;
    asm("{ .reg .u64 t; cvta.to.shared.u64 t, %1; cvt.u32.u64 %0, t; }" : "=r"(a) : "l"(p));
    return a;
}
__device__ __forceinline__ void cp_async16(uint32_t dst, const void* src) {
    asm volatile("cp.async.cg.shared.global [%0], [%1], 16;" :: "r"(dst), "l"(src) : "memory");
}
__device__ __forceinline__ void cp_commit() {
    asm volatile("cp.async.commit_group;" ::: "memory");
}
__device__ __forceinline__ void ldsm_x4(uint32_t* r, uint32_t addr) {
    asm volatile("ldmatrix.sync.aligned.m8n8.x4.shared.b16 {%0,%1,%2,%3}, [%4];"
                 : "=r"(r[0]), "=r"(r[1]), "=r"(r[2]), "=r"(r[3]) : "r"(addr));
}
__device__ __forceinline__ void ldsm_x4_t(uint32_t* r, uint32_t addr) {
    asm volatile("ldmatrix.sync.aligned.m8n8.x4.trans.shared.b16 {%0,%1,%2,%3}, [%4];"
                 : "=r"(r[0]), "=r"(r[1]), "=r"(r[2]), "=r"(r[3]) : "r"(addr));
}
__device__ __forceinline__ void mma_bf16(float* d, const uint32_t* a, uint32_t b0, uint32_t b1) {
    asm volatile(
        "mma.sync.aligned.m16n8k16.row.col.f32.bf16.bf16.f32 "
        "{%0,%1,%2,%3}, {%4,%5,%6,%7}, {%8,%9}, {%0,%1,%2,%3};"
        : "+f"(d[0]), "+f"(d[1]), "+f"(d[2]), "+f"(d[3])
        : "r"(a[0]), "r"(a[1]), "r"(a[2]), "r"(a[3]), "r"(b0), "r"(b1));
}
// pack two fp32 into bf16x2: lo half = first arg
__device__ __forceinline__ uint32_t pack2(float lo, float hi) {
    uint32_t r;
    asm("cvt.rn.bf16x2.f32 %0, %1, %2;" : "=r"(r) : "f"(hi), "f"(lo));
    return r;
}
__device__ __forceinline__ void split1(float v, float& h, float& l) {
    h = __bfloat162float(__float2bfloat16(v));
    l = v - h;
}
__device__ __forceinline__ float ex2(float x) {
    float r; asm("ex2.approx.f32 %0, %1;" : "=f"(r) : "f"(x)); return r;
}

// ---------------- split conversions ----------------
__global__ void split_f32(const float4* __restrict__ x, __nv_bfloat16* __restrict__ hi,
                          __nv_bfloat16* __restrict__ lo, int n4) {
    int i = blockIdx.x * blockDim.x + threadIdx.x;
    if (i >= n4) return;
    float4 v = x[i];
    float h0, h1, h2, h3, l0, l1, l2, l3;
    split1(v.x, h0, l0); split1(v.y, h1, l1);
    split1(v.z, h2, l2); split1(v.w, h3, l3);
    ((uint32_t*)hi)[2 * i]     = pack2(h0, h1);
    ((uint32_t*)hi)[2 * i + 1] = pack2(h2, h3);
    ((uint32_t*)lo)[2 * i]     = pack2(l0, l1);
    ((uint32_t*)lo)[2 * i + 1] = pack2(l2, l3);
}

// W [K,N] -> W^T split: hiT/loT [N][K]
__global__ void split_w_T(const float* __restrict__ W, __nv_bfloat16* __restrict__ hiT,
                          __nv_bfloat16* __restrict__ loT) {
    __shared__ float t[32][33];
    int n0 = blockIdx.x * 32, k0 = blockIdx.y * 32;
    int tx = threadIdx.x, ty = threadIdx.y;   // 32 x 8
    #pragma unroll
    for (int i = ty; i < 32; i += 8) t[i][tx] = W[(size_t)(k0 + i) * DIM + n0 + tx];
    __syncthreads();
    #pragma unroll
    for (int i = ty; i < 32; i += 8) {
        float v = t[tx][i];
        float h, l; split1(v, h, l);
        hiT[(size_t)(n0 + i) * DIM + k0 + tx] = __float2bfloat16(h);
        loT[(size_t)(n0 + i) * DIM + k0 + tx] = __float2bfloat16(l);
    }
}

// ---------------- cond MLP ----------------
__global__ void cond_mlp1(const float* __restrict__ cond, const float* __restrict__ Wc1,
                          const float* __restrict__ bc1, float* __restrict__ h) {
    int b = blockIdx.x;
    int j = threadIdx.x;
    float acc = bc1[j];
    const float* cr = cond + b * CL;
    #pragma unroll 8
    for (int k = 0; k < CL; k++) acc = fmaf(cr[k], Wc1[k * HID + j], acc);
    h[b * HID + j] = acc > 0.f ? acc : 0.f;
}
__global__ void cond_mlp2(const float* __restrict__ h, const float* __restrict__ Wc2,
                          float* __restrict__ c) {
    int b = blockIdx.x;
    int n = threadIdx.x;
    float acc = 0.f;
    const float* hr = h + b * HID;
    #pragma unroll 8
    for (int k = 0; k < HID; k++) acc = fmaf(hr[k], Wc2[k * DIM + n], acc);
    c[b * DIM + n] = acc;
}

// ---------------- mma.sync split-bf16 GEMM ----------------
#define KC 64
#define NCHUNK (DIM / KC)                // 16
#define TPITCH 144
#define TILE_BYTES (128 * TPITCH)        // 18432
#define STAGE_BYTES (4 * TILE_BYTES)     // 73728
#define GEMM_SMEM (2 * STAGE_BYTES)      // 147456

__device__ __forceinline__ void load_chunk(uint32_t stg, const __nv_bfloat16* Ahi,
                                           const __nv_bfloat16* Alo, const __nv_bfloat16* BhiT,
                                           const __nv_bfloat16* BloT, int bm, int bn, int k0, int tid) {
    #pragma unroll
    for (int i = 0; i < 4; i++) {
        int idx = tid + i * 256;
        int r = idx >> 3;
        int c = (idx & 7) << 4;
        uint32_t dst = (uint32_t)(r * TPITCH + c);
        cp_async16(stg + 0 * TILE_BYTES + dst, (const char*)(Ahi  + (size_t)(bm + r) * DIM + k0) + c);
        cp_async16(stg + 1 * TILE_BYTES + dst, (const char*)(Alo  + (size_t)(bm + r) * DIM + k0) + c);
        cp_async16(stg + 2 * TILE_BYTES + dst, (const char*)(BhiT + (size_t)(bn + r) * DIM + k0) + c);
        cp_async16(stg + 3 * TILE_BYTES + dst, (const char*)(BloT + (size_t)(bn + r) * DIM + k0) + c);
    }
    cp_commit();
}

// Cf!=null: fp32 output. Else: split-bf16 output to Chi/Clo.
__global__ __launch_bounds__(256, 1)
void gemm_mma(const __nv_bfloat16* __restrict__ Ahi, const __nv_bfloat16* __restrict__ Alo,
              const __nv_bfloat16* __restrict__ BhiT, const __nv_bfloat16* __restrict__ BloT,
              const float* __restrict__ bias, const float* __restrict__ cb,
              float* __restrict__ Cf, __nv_bfloat16* __restrict__ Chi,
              __nv_bfloat16* __restrict__ Clo, int S) {
    extern __shared__ char smem[];
    uint32_t sbase = smem_u32(smem);
    const int tid = threadIdx.x;
    const int lane = tid & 31, wid = tid >> 5;
    const int wm = wid & 3;
    const int wn = wid >> 2;
    const int bm = blockIdx.y * 128, bn = blockIdx.x * 128;

    float acc[2][8][4];
    #pragma unroll
    for (int mb = 0; mb < 2; mb++)
        #pragma unroll
        for (int j = 0; j < 8; j++)
            #pragma unroll
            for (int r = 0; r < 4; r++) acc[mb][j][r] = 0.f;

    const int alr = lane & 15, alh = lane >> 4;
    const int bnr = (lane & 7) + (lane >> 4) * 8;
    const int bkh = (lane >> 3) & 1;

    load_chunk(sbase,               Ahi, Alo, BhiT, BloT, bm, bn, 0,  tid);
    load_chunk(sbase + STAGE_BYTES, Ahi, Alo, BhiT, BloT, bm, bn, KC, tid);

    for (int i = 0; i < NCHUNK; i++) {
        if (i == NCHUNK - 1) asm volatile("cp.async.wait_group 0;" ::: "memory");
        else                 asm volatile("cp.async.wait_group 1;" ::: "memory");
        __syncthreads();

        const uint32_t stg   = sbase + (uint32_t)(i & 1) * STAGE_BYTES;
        const uint32_t ahi_b = stg + wm * 32 * TPITCH;
        const uint32_t bhi_b = stg + 2 * TILE_BYTES + wn * 64 * TPITCH;

        #pragma unroll
        for (int kb = 0; kb < 4; kb++) {
            const uint32_t koff = kb * 32;
            uint32_t ah[2][4], al[2][4];
            #pragma unroll
            for (int mb = 0; mb < 2; mb++) {
                uint32_t aaddr = ahi_b + (uint32_t)((mb * 16 + alr) * TPITCH) + koff + alh * 16;
                ldsm_x4(ah[mb], aaddr);
                ldsm_x4(al[mb], aaddr + TILE_BYTES);
            }
            uint32_t bh[4][4], bl[4][4];
            #pragma unroll
            for (int g = 0; g < 4; g++) {
                uint32_t baddr = bhi_b + (uint32_t)((g * 16 + bnr) * TPITCH) + koff + bkh * 16;
                ldsm_x4(bh[g], baddr);
                ldsm_x4(bl[g], baddr + TILE_BYTES);
            }
            #pragma unroll
            for (int mb = 0; mb < 2; mb++)
                #pragma unroll
                for (int g = 0; g < 4; g++)
                    #pragma unroll
                    for (int h = 0; h < 2; h++) {
                        float* d = acc[mb][g * 2 + h];
                        mma_bf16(d, ah[mb], bh[g][2 * h], bh[g][2 * h + 1]);
                        mma_bf16(d, ah[mb], bl[g][2 * h], bl[g][2 * h + 1]);
                        mma_bf16(d, al[mb], bh[g][2 * h], bh[g][2 * h + 1]);
                    }
        }
        __syncthreads();
        if (i + 2 < NCHUNK)
            load_chunk(stg, Ahi, Alo, BhiT, BloT, bm, bn, (i + 2) * KC, tid);
    }

    const int qr = lane >> 2, qc = lane & 3;
    const int batch = bm / S;
    const float* cbr = cb ? (cb + (size_t)batch * DIM) : nullptr;
    #pragma unroll
    for (int mb = 0; mb < 2; mb++) {
        const int row0 = bm + wm * 32 + mb * 16 + qr;
        #pragma unroll
        for (int j = 0; j < 8; j++) {
            const int col = bn + wn * 64 + j * 8 + qc * 2;
            float b0 = bias[col], b1 = bias[col + 1];
            if (cbr) { b0 += cbr[col]; b1 += cbr[col + 1]; }
            float v0 = acc[mb][j][0] + b0, v1 = acc[mb][j][1] + b1;
            float v2 = acc[mb][j][2] + b0, v3 = acc[mb][j][3] + b1;
            if (Cf) {
                *(float2*)(Cf + (size_t)row0 * DIM + col)       = make_float2(v0, v1);
                *(float2*)(Cf + (size_t)(row0 + 8) * DIM + col) = make_float2(v2, v3);
            } else {
                float h0, h1, h2, h3, l0, l1, l2, l3;
                split1(v0, h0, l0); split1(v1, h1, l1);
                split1(v2, h2, l2); split1(v3, h3, l3);
                *(uint32_t*)(Chi + (size_t)row0 * DIM + col)       = pack2(h0, h1);
                *(uint32_t*)(Clo + (size_t)row0 * DIM + col)       = pack2(l0, l1);
                *(uint32_t*)(Chi + (size_t)(row0 + 8) * DIM + col) = pack2(h2, h3);
                *(uint32_t*)(Clo + (size_t)(row0 + 8) * DIM + col) = pack2(l2, l3);
            }
        }
    }
}

// ---------------- flash attention with mma.sync (split-bf16) ----------------
// Br=128 (8 warps x 16 rows), Bc=64, dk=64. 2-stage cp.async KV pipeline.
#define ABC 64
#define KVP 144                        // smem pitch bytes (64 bf16 + pad)
#define ATILE (ABC * KVP)              // 9216
#define ASTAGE (4 * ATILE)             // khi,klo,vhi,vlo = 36864
#define FA_SMEM (2 * ASTAGE)           // 73728
#define NKBLK (SEQ / ABC)              // 32

__device__ __forceinline__ void load_kv(uint32_t stg,
        const __nv_bfloat16* khi, const __nv_bfloat16* klo,
        const __nv_bfloat16* vhi, const __nv_bfloat16* vlo,
        size_t rowbase, int kbase, int tid) {
    #pragma unroll
    for (int i = 0; i < 8; i++) {
        int idx = tid + i * 256;              // 0..2047
        int t = i >> 1;                       // tile: 0=khi 1=klo 2=vhi 3=vlo
        int r = (idx >> 3) & 63;
        int c = (idx & 7) << 4;               // byte col
        const __nv_bfloat16* src = (t == 0) ? khi : (t == 1) ? klo : (t == 2) ? vhi : vlo;
        cp_async16(stg + (uint32_t)(t * ATILE + r * KVP + c),
                   (const char*)(src + rowbase + (size_t)(kbase + r) * DIM) + c);
    }
    cp_commit();
}

__global__ __launch_bounds__(256, 1)
void flash_mma(const __nv_bfloat16* __restrict__ qhi, const __nv_bfloat16* __restrict__ qlo,
               const __nv_bfloat16* __restrict__ khi, const __nv_bfloat16* __restrict__ klo,
               const __nv_bfloat16* __restrict__ vhi, const __nv_bfloat16* __restrict__ vlo,
               __nv_bfloat16* __restrict__ xhi, __nv_bfloat16* __restrict__ xlo) {
    extern __shared__ char smem[];
    uint32_t sbase = smem_u32(smem);
    const int tid = threadIdx.x;
    const int lane = tid & 31, w = tid >> 5;
    const int qr = lane >> 2, qc = lane & 3;

    const int qb = blockIdx.x;                // 0..15
    const int bh = blockIdx.y;                // 0..31
    const int b = bh >> 4, h = bh & 15;
    const size_t rowbase = (size_t)b * SEQ * DIM + h * DK;
    const int r0 = qb * 128 + w * 16 + qr;    // this thread's first q row
    const int r1 = r0 + 8;

    // ldmatrix lane constants
    const int bnr = (lane & 7) + (lane >> 4) * 8;        // K (non-trans): n row
    const int bkh = (lane >> 3) & 1;                     // K: k-half
    const int vkr = (lane & 7) + (((lane >> 3) & 1) << 3); // V (trans): k row
    const int vnc = lane >> 4;                           // V: n chunk

    // Q fragments (registers, loaded once from gmem)
    uint32_t qh_[4][4], ql_[4][4];
    {
        const __nv_bfloat16* qhp = qhi + rowbase;
        const __nv_bfloat16* qlp = qlo + rowbase;
        #pragma unroll
        for (int kk = 0; kk < 4; kk++) {
            int c0 = kk * 16 + 2 * qc, c1 = c0 + 8;
            qh_[kk][0] = *(const uint32_t*)(qhp + (size_t)r0 * DIM + c0);
            qh_[kk][1] = *(const uint32_t*)(qhp + (size_t)r1 * DIM + c0);
            qh_[kk][2] = *(const uint32_t*)(qhp + (size_t)r0 * DIM + c1);
            qh_[kk][3] = *(const uint32_t*)(qhp + (size_t)r1 * DIM + c1);
            ql_[kk][0] = *(const uint32_t*)(qlp + (size_t)r0 * DIM + c0);
            ql_[kk][1] = *(const uint32_t*)(qlp + (size_t)r1 * DIM + c0);
            ql_[kk][2] = *(const uint32_t*)(qlp + (size_t)r0 * DIM + c1);
            ql_[kk][3] = *(const uint32_t*)(qlp + (size_t)r1 * DIM + c1);
        }
    }

    load_kv(sbase,          khi, klo, vhi, vlo, rowbase, 0,   tid);
    load_kv(sbase + ASTAGE, khi, klo, vhi, vlo, rowbase, ABC, tid);

    float o[8][4];
    #pragma unroll
    for (int j = 0; j < 8; j++)
        #pragma unroll
        for (int r = 0; r < 4; r++) o[j][r] = 0.f;
    float m0 = -1e30f, m1 = -1e30f, l0 = 0.f, l1 = 0.f;
    const float C = 0.125f * 1.4426950408889634f;   // scale * log2(e)

    for (int blk = 0; blk < NKBLK; blk++) {
        if (blk == NKBLK - 1) asm volatile("cp.async.wait_group 0;" ::: "memory");
        else                  asm volatile("cp.async.wait_group 1;" ::: "memory");
        __syncthreads();
        const uint32_t stg = sbase + (uint32_t)(blk & 1) * ASTAGE;

        // ---- S = Q K^T (split, 3 terms) ----
        float s[8][4];
        #pragma unroll
        for (int j = 0; j < 8; j++)
            #pragma unroll
            for (int r = 0; r < 4; r++) s[j][r] = 0.f;

        #pragma unroll
        for (int kk = 0; kk < 4; kk++) {
            const uint32_t koff = kk * 32;
            uint32_t bhf[4][4], blf[4][4];
            #pragma unroll
            for (int g = 0; g < 4; g++) {
                uint32_t addr = stg + (uint32_t)((g * 16 + bnr) * KVP) + koff + bkh * 16;
                ldsm_x4(bhf[g], addr);
                ldsm_x4(blf[g], addr + ATILE);
            }
            #pragma unroll
            for (int g = 0; g < 4; g++)
                #pragma unroll
                for (int h2 = 0; h2 < 2; h2++) {
                    float* d = s[g * 2 + h2];
                    mma_bf16(d, qh_[kk], bhf[g][2 * h2], bhf[g][2 * h2 + 1]);
                    mma_bf16(d, qh_[kk], blf[g][2 * h2], blf[g][2 * h2 + 1]);
                    mma_bf16(d, ql_[kk], bhf[g][2 * h2], bhf[g][2 * h2 + 1]);
                }
        }

        // ---- online softmax (register, quad shfl) ----
        float mx0 = -1e30f, mx1 = -1e30f;
        #pragma unroll
        for (int j = 0; j < 8; j++) {
            mx0 = fmaxf(mx0, fmaxf(s[j][0], s[j][1]));
            mx1 = fmaxf(mx1, fmaxf(s[j][2], s[j][3]));
        }
        mx0 = fmaxf(mx0, __shfl_xor_sync(0xFFFFFFFFu, mx0, 1));
        mx0 = fmaxf(mx0, __shfl_xor_sync(0xFFFFFFFFu, mx0, 2));
        mx1 = fmaxf(mx1, __shfl_xor_sync(0xFFFFFFFFu, mx1, 1));
        mx1 = fmaxf(mx1, __shfl_xor_sync(0xFFFFFFFFu, mx1, 2));
        float mn0 = fmaxf(m0, mx0), mn1 = fmaxf(m1, mx1);
        float a0 = ex2((m0 - mn0) * C), a1 = ex2((m1 - mn1) * C);
        m0 = mn0; m1 = mn1;

        float rs0 = 0.f, rs1 = 0.f;
        #pragma unroll
        for (int j = 0; j < 8; j++) {
            s[j][0] = ex2((s[j][0] - m0) * C);
            s[j][1] = ex2((s[j][1] - m0) * C);
            s[j][2] = ex2((s[j][2] - m1) * C);
            s[j][3] = ex2((s[j][3] - m1) * C);
            rs0 += s[j][0] + s[j][1];
            rs1 += s[j][2] + s[j][3];
        }
        rs0 += __shfl_xor_sync(0xFFFFFFFFu, rs0, 1);
        rs0 += __shfl_xor_sync(0xFFFFFFFFu, rs0, 2);
        rs1 += __shfl_xor_sync(0xFFFFFFFFu, rs1, 1);
        rs1 += __shfl_xor_sync(0xFFFFFFFFu, rs1, 2);
        l0 = l0 * a0 + rs0;
        l1 = l1 * a1 + rs1;
        #pragma unroll
        for (int j = 0; j < 8; j++) {
            o[j][0] *= a0; o[j][1] *= a0;
            o[j][2] *= a1; o[j][3] *= a1;
        }

        // ---- convert P to split-bf16 A-fragments (pure register) ----
        uint32_t ph[4][4], pl[4][4];
        #pragma unroll
        for (int kk = 0; kk < 4; kk++) {
            float h00, h01, h10, h11, lo00, lo01, lo10, lo11;
            // tile 2kk -> a0 (rows qr, k=16kk+2qc) & a1 (rows qr+8)
            split1(s[2 * kk][0], h00, lo00); split1(s[2 * kk][1], h01, lo01);
            split1(s[2 * kk][2], h10, lo10); split1(s[2 * kk][3], h11, lo11);
            ph[kk][0] = pack2(h00, h01); pl[kk][0] = pack2(lo00, lo01);
            ph[kk][1] = pack2(h10, h11); pl[kk][1] = pack2(lo10, lo11);
            // tile 2kk+1 -> a2, a3 (k=16kk+8+2qc)
            split1(s[2 * kk + 1][0], h00, lo00); split1(s[2 * kk + 1][1], h01, lo01);
            split1(s[2 * kk + 1][2], h10, lo10); split1(s[2 * kk + 1][3], h11, lo11);
            ph[kk][2] = pack2(h00, h01); pl[kk][2] = pack2(lo00, lo01);
            ph[kk][3] = pack2(h10, h11); pl[kk][3] = pack2(lo10, lo11);
        }

        // ---- O += P V (split, 3 terms); V via ldmatrix.trans ----
        #pragma unroll
        for (int kk = 0; kk < 4; kk++) {
            uint32_t bhf[4][4], blf[4][4];
            #pragma unroll
            for (int g = 0; g < 4; g++) {
                uint32_t addr = stg + 2 * ATILE + (uint32_t)((kk * 16 + vkr) * KVP) + g * 32 + vnc * 16;
                ldsm_x4_t(bhf[g], addr);
                ldsm_x4_t(blf[g], addr + ATILE);
            }
            #pragma unroll
            for (int g = 0; g < 4; g++)
                #pragma unroll
                for (int h2 = 0; h2 < 2; h2++) {
                    float* d = o[g * 2 + h2];
                    mma_bf16(d, ph[kk], bhf[g][2 * h2], bhf[g][2 * h2 + 1]);
                    mma_bf16(d, ph[kk], blf[g][2 * h2], blf[g][2 * h2 + 1]);
                    mma_bf16(d, pl[kk], bhf[g][2 * h2], bhf[g][2 * h2 + 1]);
                }
        }

        __syncthreads();
        if (blk + 2 < NKBLK)
            load_kv(stg, khi, klo, vhi, vlo, rowbase, (blk + 2) * ABC, tid);
    }

    // ---- epilogue: normalize, split to bf16, store ----
    const float inv0 = 1.f / l0, inv1 = 1.f / l1;
    #pragma unroll
    for (int j = 0; j < 8; j++) {
        const int col = j * 8 + 2 * qc;
        float v0 = o[j][0] * inv0, v1 = o[j][1] * inv0;
        float v2 = o[j][2] * inv1, v3 = o[j][3] * inv1;
        float h0, h1, h2, h3, lo0, lo1, lo2, lo3;
        split1(v0, h0, lo0); split1(v1, h1, lo1);
        split1(v2, h2, lo2); split1(v3, h3, lo3);
        *(uint32_t*)(xhi + rowbase + (size_t)r0 * DIM + col) = pack2(h0, h1);
        *(uint32_t*)(xlo + rowbase + (size_t)r0 * DIM + col) = pack2(lo0, lo1);
        *(uint32_t*)(xhi + rowbase + (size_t)r1 * DIM + col) = pack2(h2, h3);
        *(uint32_t*)(xlo + rowbase + (size_t)r1 * DIM + col) = pack2(lo2, lo3);
    }
}

// ---------------- launcher ----------------
extern "C" void kernel_launch(void* const* d_in, const int* in_sizes, int n_in,
                              void* d_out, int out_size) {
    const float* query = (const float*)d_in[0];
    const float* key   = (const float*)d_in[1];
    const float* value = (const float*)d_in[2];
    const float* cond  = (const float*)d_in[3];
    const float* Wq = (const float*)d_in[4];
    const float* bq = (const float*)d_in[5];
    const float* Wk = (const float*)d_in[6];
    const float* bk = (const float*)d_in[7];
    const float* Wv = (const float*)d_in[8];
    const float* bv = (const float*)d_in[9];
    const float* Wo = (const float*)d_in[10];
    const float* bo = (const float*)d_in[11];
    const float* Wc1 = (const float*)d_in[12];
    const float* bc1 = (const float*)d_in[13];
    const float* Wc2 = (const float*)d_in[14];
    float* out = (float*)d_out;

    float *hb, *cb;
    __nv_bfloat16 *ahi, *alo, *whi, *wlo;
    __nv_bfloat16 *qhi, *qlo, *khi, *klo, *vhi, *vlo, *xhi, *xlo;
    cudaGetSymbolAddress((void**)&hb, g_h);
    cudaGetSymbolAddress((void**)&cb, g_c);
    cudaGetSymbolAddress((void**)&ahi, g_ahi);
    cudaGetSymbolAddress((void**)&alo, g_alo);
    cudaGetSymbolAddress((void**)&whi, g_whi);
    cudaGetSymbolAddress((void**)&wlo, g_wlo);
    cudaGetSymbolAddress((void**)&qhi, g_qhi);
    cudaGetSymbolAddress((void**)&qlo, g_qlo);
    cudaGetSymbolAddress((void**)&khi, g_khi);
    cudaGetSymbolAddress((void**)&klo, g_klo);
    cudaGetSymbolAddress((void**)&vhi, g_vhi);
    cudaGetSymbolAddress((void**)&vlo, g_vlo);
    cudaGetSymbolAddress((void**)&xhi, g_xhi);
    cudaGetSymbolAddress((void**)&xlo, g_xlo);

    cudaFuncSetAttribute(gemm_mma,  cudaFuncAttributeMaxDynamicSharedMemorySize, GEMM_SMEM);
    cudaFuncSetAttribute(flash_mma, cudaFuncAttributeMaxDynamicSharedMemorySize, FA_SMEM);

    const int n4 = MROWS * DIM / 4;
    dim3 tgrid(DIM / 32, DIM / 32), tblk(32, 8);
    dim3 ggrid(DIM / 128, MROWS / 128);

    cond_mlp1<<<BATCH, HID>>>(cond, Wc1, bc1, hb);
    cond_mlp2<<<BATCH, DIM>>>(hb, Wc2, cb);

    // Q projection -> split bf16
    split_w_T<<<tgrid, tblk>>>(Wq, whi, wlo);
    split_f32<<<n4 / 256, 256>>>((const float4*)query, ahi, alo, n4);
    gemm_mma<<<ggrid, 256, GEMM_SMEM>>>(ahi, alo, whi, wlo, bq, nullptr, nullptr, qhi, qlo, SEQ);

    // K projection -> split bf16
    split_w_T<<<tgrid, tblk>>>(Wk, whi, wlo);
    split_f32<<<n4 / 256, 256>>>((const float4*)key, ahi, alo, n4);
    gemm_mma<<<ggrid, 256, GEMM_SMEM>>>(ahi, alo, whi, wlo, bk, nullptr, nullptr, khi, klo, SEQ);

    // V projection (+ cond bias) -> split bf16
    split_w_T<<<tgrid, tblk>>>(Wv, whi, wlo);
    split_f32<<<n4 / 256, 256>>>((const float4*)value, ahi, alo, n4);
    gemm_mma<<<ggrid, 256, GEMM_SMEM>>>(ahi, alo, whi, wlo, bv, cb, nullptr, vhi, vlo, SEQ);

    // attention -> split bf16 x
    flash_mma<<<dim3(SEQ / 128, BATCH * HEADS), 256, FA_SMEM>>>(qhi, qlo, khi, klo, vhi, vlo, xhi, xlo);

    // output projection -> fp32 out
    split_w_T<<<tgrid, tblk>>>(Wo, whi, wlo);
    gemm_mma<<<ggrid, 256, GEMM_SMEM>>>(xhi, xlo, whi, wlo, bo, nullptr, out, nullptr, nullptr, SEQ);
}

// round 13
// speedup vs baseline: 2.8016x; 1.0090x over previous
#include <cuda_runtime.h>
#include <cuda_bf16.h>
#include <cstdint>

// Problem constants
#define BATCH 2
#define SEQ   2048
#define DIM   1024
#define HEADS 16
#define DK    64
#define CL    256
#define HID   512
#define MROWS (BATCH*SEQ)   // 4096

// ---------------- scratch (device globals; no allocation allowed) ----------------
__device__ float g_h[BATCH * HID];
__device__ float g_c[BATCH * DIM];
__device__ __nv_bfloat16 g_ahi[MROWS * DIM];
__device__ __nv_bfloat16 g_alo[MROWS * DIM];
__device__ __nv_bfloat16 g_whi[DIM * DIM];   // transposed: [N][K]
__device__ __nv_bfloat16 g_wlo[DIM * DIM];
__device__ __nv_bfloat16 g_qhi[MROWS * DIM];
__device__ __nv_bfloat16 g_qlo[MROWS * DIM];
__device__ __nv_bfloat16 g_khi[MROWS * DIM];
__device__ __nv_bfloat16 g_klo[MROWS * DIM];
__device__ __nv_bfloat16 g_vhi[MROWS * DIM];
__device__ __nv_bfloat16 g_vlo[MROWS * DIM];
__device__ __nv_bfloat16 g_xhi[MROWS * DIM];
__device__ __nv_bfloat16 g_xlo[MROWS * DIM];

// ================= PTX helpers (baseline PTX only) =================
__device__ __forceinline__ uint32_t smem_u32(const void* p) {
    uint32_t a;
    asm("{ .reg .u64 t; cvta.to.shared.u64 t, %1; cvt.u32.u64 %0, t; }" : "=r"(a) : "l"(p));
    return a;
}
__device__ __forceinline__ void cp_async16(uint32_t dst, const void* src) {
    asm volatile("cp.async.cg.shared.global [%0], [%1], 16;" :: "r"(dst), "l"(src) : "memory");
}
__device__ __forceinline__ void cp_commit() {
    asm volatile("cp.async.commit_group;" ::: "memory");
}
__device__ __forceinline__ void ldsm_x4(uint32_t* r, uint32_t addr) {
    asm volatile("ldmatrix.sync.aligned.m8n8.x4.shared.b16 {%0,%1,%2,%3}, [%4];"
                 : "=r"(r[0]), "=r"(r[1]), "=r"(r[2]), "=r"(r[3]) : "r"(addr));
}
__device__ __forceinline__ void ldsm_x4_t(uint32_t* r, uint32_t addr) {
    asm volatile("ldmatrix.sync.aligned.m8n8.x4.trans.shared.b16 {%0,%1,%2,%3}, [%4];"
                 : "=r"(r[0]), "=r"(r[1]), "=r"(r[2]), "=r"(r[3]) : "r"(addr));
}
__device__ __forceinline__ void mma_bf16(float* d, const uint32_t* a, uint32_t b0, uint32_t b1) {
    asm volatile(
        "mma.sync.aligned.m16n8k16.row.col.f32.bf16.bf16.f32 "
        "{%0,%1,%2,%3}, {%4,%5,%6,%7}, {%8,%9}, {%0,%1,%2,%3};"
        : "+f"(d[0]), "+f"(d[1]), "+f"(d[2]), "+f"(d[3])
        : "r"(a[0]), "r"(a[1]), "r"(a[2]), "r"(a[3]), "r"(b0), "r"(b1));
}
// pack two fp32 into bf16x2: lo half = first arg
__device__ __forceinline__ uint32_t pack2(float lo, float hi) {
    uint32_t r;
    asm("cvt.rn.bf16x2.f32 %0, %1, %2;" : "=r"(r) : "f"(hi), "f"(lo));
    return r;
}
__device__ __forceinline__ void split1(float v, float& h, float& l) {
    h = __bfloat162float(__float2bfloat16(v));
    l = v - h;
}
__device__ __forceinline__ float ex2(float x) {
    float r; asm("ex2.approx.f32 %0, %1;" : "=f"(r) : "f"(x)); return r;
}

// ---------------- split conversions ----------------
__global__ void split_f32(const float4* __restrict__ x, __nv_bfloat16* __restrict__ hi,
                          __nv_bfloat16* __restrict__ lo, int n4) {
    int i = blockIdx.x * blockDim.x + threadIdx.x;
    if (i >= n4) return;
    float4 v = x[i];
    float h0, h1, h2, h3, l0, l1, l2, l3;
    split1(v.x, h0, l0); split1(v.y, h1, l1);
    split1(v.z, h2, l2); split1(v.w, h3, l3);
    ((uint32_t*)hi)[2 * i]     = pack2(h0, h1);
    ((uint32_t*)hi)[2 * i + 1] = pack2(h2, h3);
    ((uint32_t*)lo)[2 * i]     = pack2(l0, l1);
    ((uint32_t*)lo)[2 * i + 1] = pack2(l2, l3);
}

// W [K,N] -> W^T split: hiT/loT [N][K]
__global__ void split_w_T(const float* __restrict__ W, __nv_bfloat16* __restrict__ hiT,
                          __nv_bfloat16* __restrict__ loT) {
    __shared__ float t[32][33];
    int n0 = blockIdx.x * 32, k0 = blockIdx.y * 32;
    int tx = threadIdx.x, ty = threadIdx.y;   // 32 x 8
    #pragma unroll
    for (int i = ty; i < 32; i += 8) t[i][tx] = W[(size_t)(k0 + i) * DIM + n0 + tx];
    __syncthreads();
    #pragma unroll
    for (int i = ty; i < 32; i += 8) {
        float v = t[tx][i];
        float h, l; split1(v, h, l);
        hiT[(size_t)(n0 + i) * DIM + k0 + tx] = __float2bfloat16(h);
        loT[(size_t)(n0 + i) * DIM + k0 + tx] = __float2bfloat16(l);
    }
}

// ---------------- cond MLP ----------------
__global__ void cond_mlp1(const float* __restrict__ cond, const float* __restrict__ Wc1,
                          const float* __restrict__ bc1, float* __restrict__ h) {
    int b = blockIdx.x;
    int j = threadIdx.x;
    float acc = bc1[j];
    const float* cr = cond + b * CL;
    #pragma unroll 8
    for (int k = 0; k < CL; k++) acc = fmaf(cr[k], Wc1[k * HID + j], acc);
    h[b * HID + j] = acc > 0.f ? acc : 0.f;
}
__global__ void cond_mlp2(const float* __restrict__ h, const float* __restrict__ Wc2,
                          float* __restrict__ c) {
    int b = blockIdx.x;
    int n = threadIdx.x;
    float acc = 0.f;
    const float* hr = h + b * HID;
    #pragma unroll 8
    for (int k = 0; k < HID; k++) acc = fmaf(hr[k], Wc2[k * DIM + n], acc);
    c[b * DIM + n] = acc;
}

// ---------------- mma.sync split-bf16 GEMM (3-stage, early load issue) ----------------
#define KC 64
#define NCHUNK (DIM / KC)                // 16
#define TPITCH 144
#define TILE_BYTES (128 * TPITCH)        // 18432
#define STAGE_BYTES (4 * TILE_BYTES)     // 73728
#define GEMM_SMEM (3 * STAGE_BYTES)      // 221184

__device__ __forceinline__ void load_chunk(uint32_t stg, const __nv_bfloat16* Ahi,
                                           const __nv_bfloat16* Alo, const __nv_bfloat16* BhiT,
                                           const __nv_bfloat16* BloT, int bm, int bn, int k0, int tid) {
    #pragma unroll
    for (int i = 0; i < 4; i++) {
        int idx = tid + i * 256;
        int r = idx >> 3;
        int c = (idx & 7) << 4;
        uint32_t dst = (uint32_t)(r * TPITCH + c);
        cp_async16(stg + 0 * TILE_BYTES + dst, (const char*)(Ahi  + (size_t)(bm + r) * DIM + k0) + c);
        cp_async16(stg + 1 * TILE_BYTES + dst, (const char*)(Alo  + (size_t)(bm + r) * DIM + k0) + c);
        cp_async16(stg + 2 * TILE_BYTES + dst, (const char*)(BhiT + (size_t)(bn + r) * DIM + k0) + c);
        cp_async16(stg + 3 * TILE_BYTES + dst, (const char*)(BloT + (size_t)(bn + r) * DIM + k0) + c);
    }
    cp_commit();
}

// Cf!=null: fp32 output. Else: split-bf16 output to Chi/Clo.
__global__ __launch_bounds__(256, 1)
void gemm_mma(const __nv_bfloat16* __restrict__ Ahi, const __nv_bfloat16* __restrict__ Alo,
              const __nv_bfloat16* __restrict__ BhiT, const __nv_bfloat16* __restrict__ BloT,
              const float* __restrict__ bias, const float* __restrict__ cb,
              float* __restrict__ Cf, __nv_bfloat16* __restrict__ Chi,
              __nv_bfloat16* __restrict__ Clo, int S) {
    extern __shared__ char smem[];
    uint32_t sbase = smem_u32(smem);
    const int tid = threadIdx.x;
    const int lane = tid & 31, wid = tid >> 5;
    const int wm = wid & 3;
    const int wn = wid >> 2;
    const int bm = blockIdx.y * 128, bn = blockIdx.x * 128;

    float acc[2][8][4];
    #pragma unroll
    for (int mb = 0; mb < 2; mb++)
        #pragma unroll
        for (int j = 0; j < 8; j++)
            #pragma unroll
            for (int r = 0; r < 4; r++) acc[mb][j][r] = 0.f;

    const int alr = lane & 15, alh = lane >> 4;
    const int bnr = (lane & 7) + (lane >> 4) * 8;
    const int bkh = (lane >> 3) & 1;

    load_chunk(sbase,               Ahi, Alo, BhiT, BloT, bm, bn, 0,  tid);
    load_chunk(sbase + STAGE_BYTES, Ahi, Alo, BhiT, BloT, bm, bn, KC, tid);

    int stg_i = 0, stg_n = 2;   // stage of chunk i; stage where chunk i+2 goes
    for (int i = 0; i < NCHUNK; i++) {
        __syncthreads();                         // readers of stage stg_n (chunk i-1) done
        if (i + 2 < NCHUNK)
            load_chunk(sbase + (uint32_t)stg_n * STAGE_BYTES,
                       Ahi, Alo, BhiT, BloT, bm, bn, (i + 2) * KC, tid);
        if (i + 2 < NCHUNK)       asm volatile("cp.async.wait_group 2;" ::: "memory");
        else if (i + 2 == NCHUNK) asm volatile("cp.async.wait_group 1;" ::: "memory");
        else                      asm volatile("cp.async.wait_group 0;" ::: "memory");
        __syncthreads();                         // chunk i data visible to all

        const uint32_t stg   = sbase + (uint32_t)stg_i * STAGE_BYTES;
        const uint32_t ahi_b = stg + wm * 32 * TPITCH;
        const uint32_t bhi_b = stg + 2 * TILE_BYTES + wn * 64 * TPITCH;

        #pragma unroll
        for (int kb = 0; kb < 4; kb++) {
            const uint32_t koff = kb * 32;
            uint32_t ah[2][4], al[2][4];
            #pragma unroll
            for (int mb = 0; mb < 2; mb++) {
                uint32_t aaddr = ahi_b + (uint32_t)((mb * 16 + alr) * TPITCH) + koff + alh * 16;
                ldsm_x4(ah[mb], aaddr);
                ldsm_x4(al[mb], aaddr + TILE_BYTES);
            }
            uint32_t bh[4][4], bl[4][4];
            #pragma unroll
            for (int g = 0; g < 4; g++) {
                uint32_t baddr = bhi_b + (uint32_t)((g * 16 + bnr) * TPITCH) + koff + bkh * 16;
                ldsm_x4(bh[g], baddr);
                ldsm_x4(bl[g], baddr + TILE_BYTES);
            }
            #pragma unroll
            for (int mb = 0; mb < 2; mb++)
                #pragma unroll
                for (int g = 0; g < 4; g++)
                    #pragma unroll
                    for (int h = 0; h < 2; h++) {
                        float* d = acc[mb][g * 2 + h];
                        mma_bf16(d, ah[mb], bh[g][2 * h], bh[g][2 * h + 1]);
                        mma_bf16(d, ah[mb], bl[g][2 * h], bl[g][2 * h + 1]);
                        mma_bf16(d, al[mb], bh[g][2 * h], bh[g][2 * h + 1]);
                    }
        }
        stg_i = (stg_i == 2) ? 0 : stg_i + 1;
        stg_n = (stg_n == 2) ? 0 : stg_n + 1;
    }

    const int qr = lane >> 2, qc = lane & 3;
    const int batch = bm / S;
    const float* cbr = cb ? (cb + (size_t)batch * DIM) : nullptr;
    #pragma unroll
    for (int mb = 0; mb < 2; mb++) {
        const int row0 = bm + wm * 32 + mb * 16 + qr;
        #pragma unroll
        for (int j = 0; j < 8; j++) {
            const int col = bn + wn * 64 + j * 8 + qc * 2;
            float b0 = bias[col], b1 = bias[col + 1];
            if (cbr) { b0 += cbr[col]; b1 += cbr[col + 1]; }
            float v0 = acc[mb][j][0] + b0, v1 = acc[mb][j][1] + b1;
            float v2 = acc[mb][j][2] + b0, v3 = acc[mb][j][3] + b1;
            if (Cf) {
                *(float2*)(Cf + (size_t)row0 * DIM + col)       = make_float2(v0, v1);
                *(float2*)(Cf + (size_t)(row0 + 8) * DIM + col) = make_float2(v2, v3);
            } else {
                float h0, h1, h2, h3, l0, l1, l2, l3;
                split1(v0, h0, l0); split1(v1, h1, l1);
                split1(v2, h2, l2); split1(v3, h3, l3);
                *(uint32_t*)(Chi + (size_t)row0 * DIM + col)       = pack2(h0, h1);
                *(uint32_t*)(Clo + (size_t)row0 * DIM + col)       = pack2(l0, l1);
                *(uint32_t*)(Chi + (size_t)(row0 + 8) * DIM + col) = pack2(h2, h3);
                *(uint32_t*)(Clo + (size_t)(row0 + 8) * DIM + col) = pack2(l2, l3);
            }
        }
    }
}

// ---------------- flash attention with mma.sync (split-bf16, 3-stage) ----------------
#define ABC 64
#define KVP 144
#define ATILE (ABC * KVP)              // 9216
#define ASTAGE (4 * ATILE)             // 36864
#define FA_SMEM (3 * ASTAGE)           // 110592
#define NKBLK (SEQ / ABC)              // 32

__device__ __forceinline__ void load_kv(uint32_t stg,
        const __nv_bfloat16* khi, const __nv_bfloat16* klo,
        const __nv_bfloat16* vhi, const __nv_bfloat16* vlo,
        size_t rowbase, int kbase, int tid) {
    #pragma unroll
    for (int i = 0; i < 8; i++) {
        int idx = tid + i * 256;
        int t = i >> 1;
        int r = (idx >> 3) & 63;
        int c = (idx & 7) << 4;
        const __nv_bfloat16* src = (t == 0) ? khi : (t == 1) ? klo : (t == 2) ? vhi : vlo;
        cp_async16(stg + (uint32_t)(t * ATILE + r * KVP + c),
                   (const char*)(src + rowbase + (size_t)(kbase + r) * DIM) + c);
    }
    cp_commit();
}

__global__ __launch_bounds__(256, 1)
void flash_mma(const __nv_bfloat16* __restrict__ qhi, const __nv_bfloat16* __restrict__ qlo,
               const __nv_bfloat16* __restrict__ khi, const __nv_bfloat16* __restrict__ klo,
               const __nv_bfloat16* __restrict__ vhi, const __nv_bfloat16* __restrict__ vlo,
               __nv_bfloat16* __restrict__ xhi, __nv_bfloat16* __restrict__ xlo) {
    extern __shared__ char smem[];
    uint32_t sbase = smem_u32(smem);
    const int tid = threadIdx.x;
    const int lane = tid & 31, w = tid >> 5;
    const int qr = lane >> 2, qc = lane & 3;

    const int qb = blockIdx.x;
    const int bh = blockIdx.y;
    const int b = bh >> 4, h = bh & 15;
    const size_t rowbase = (size_t)b * SEQ * DIM + h * DK;
    const int r0 = qb * 128 + w * 16 + qr;
    const int r1 = r0 + 8;

    const int bnr = (lane & 7) + (lane >> 4) * 8;
    const int bkh = (lane >> 3) & 1;
    const int vkr = (lane & 7) + (((lane >> 3) & 1) << 3);
    const int vnc = lane >> 4;

    uint32_t qh_[4][4], ql_[4][4];
    {
        const __nv_bfloat16* qhp = qhi + rowbase;
        const __nv_bfloat16* qlp = qlo + rowbase;
        #pragma unroll
        for (int kk = 0; kk < 4; kk++) {
            int c0 = kk * 16 + 2 * qc, c1 = c0 + 8;
            qh_[kk][0] = *(const uint32_t*)(qhp + (size_t)r0 * DIM + c0);
            qh_[kk][1] = *(const uint32_t*)(qhp + (size_t)r1 * DIM + c0);
            qh_[kk][2] = *(const uint32_t*)(qhp + (size_t)r0 * DIM + c1);
            qh_[kk][3] = *(const uint32_t*)(qhp + (size_t)r1 * DIM + c1);
            ql_[kk][0] = *(const uint32_t*)(qlp + (size_t)r0 * DIM + c0);
            ql_[kk][1] = *(const uint32_t*)(qlp + (size_t)r1 * DIM + c0);
            ql_[kk][2] = *(const uint32_t*)(qlp + (size_t)r0 * DIM + c1);
            ql_[kk][3] = *(const uint32_t*)(qlp + (size_t)r1 * DIM + c1);
        }
    }

    load_kv(sbase,          khi, klo, vhi, vlo, rowbase, 0,   tid);
    load_kv(sbase + ASTAGE, khi, klo, vhi, vlo, rowbase, ABC, tid);

    float o[8][4];
    #pragma unroll
    for (int j = 0; j < 8; j++)
        #pragma unroll
        for (int r = 0; r < 4; r++) o[j][r] = 0.f;
    float m0 = -1e30f, m1 = -1e30f, l0 = 0.f, l1 = 0.f;
    const float C = 0.125f * 1.4426950408889634f;

    int stg_i = 0, stg_n = 2;
    for (int blk = 0; blk < NKBLK; blk++) {
        __syncthreads();                 // readers of stage stg_n done
        if (blk + 2 < NKBLK)
            load_kv(sbase + (uint32_t)stg_n * ASTAGE, khi, klo, vhi, vlo,
                    rowbase, (blk + 2) * ABC, tid);
        if (blk + 2 < NKBLK)       asm volatile("cp.async.wait_group 2;" ::: "memory");
        else if (blk + 2 == NKBLK) asm volatile("cp.async.wait_group 1;" ::: "memory");
        else                       asm volatile("cp.async.wait_group 0;" ::: "memory");
        __syncthreads();
        const uint32_t stg = sbase + (uint32_t)stg_i * ASTAGE;

        // ---- S = Q K^T (split, 3 terms) ----
        float s[8][4];
        #pragma unroll
        for (int j = 0; j < 8; j++)
            #pragma unroll
            for (int r = 0; r < 4; r++) s[j][r] = 0.f;

        #pragma unroll
        for (int kk = 0; kk < 4; kk++) {
            const uint32_t koff = kk * 32;
            uint32_t bhf[4][4], blf[4][4];
            #pragma unroll
            for (int g = 0; g < 4; g++) {
                uint32_t addr = stg + (uint32_t)((g * 16 + bnr) * KVP) + koff + bkh * 16;
                ldsm_x4(bhf[g], addr);
                ldsm_x4(blf[g], addr + ATILE);
            }
            #pragma unroll
            for (int g = 0; g < 4; g++)
                #pragma unroll
                for (int h2 = 0; h2 < 2; h2++) {
                    float* d = s[g * 2 + h2];
                    mma_bf16(d, qh_[kk], bhf[g][2 * h2], bhf[g][2 * h2 + 1]);
                    mma_bf16(d, qh_[kk], blf[g][2 * h2], blf[g][2 * h2 + 1]);
                    mma_bf16(d, ql_[kk], bhf[g][2 * h2], bhf[g][2 * h2 + 1]);
                }
        }

        // ---- online softmax ----
        float mx0 = -1e30f, mx1 = -1e30f;
        #pragma unroll
        for (int j = 0; j < 8; j++) {
            mx0 = fmaxf(mx0, fmaxf(s[j][0], s[j][1]));
            mx1 = fmaxf(mx1, fmaxf(s[j][2], s[j][3]));
        }
        mx0 = fmaxf(mx0, __shfl_xor_sync(0xFFFFFFFFu, mx0, 1));
        mx0 = fmaxf(mx0, __shfl_xor_sync(0xFFFFFFFFu, mx0, 2));
        mx1 = fmaxf(mx1, __shfl_xor_sync(0xFFFFFFFFu, mx1, 1));
        mx1 = fmaxf(mx1, __shfl_xor_sync(0xFFFFFFFFu, mx1, 2));
        float mn0 = fmaxf(m0, mx0), mn1 = fmaxf(m1, mx1);
        float a0 = ex2((m0 - mn0) * C), a1 = ex2((m1 - mn1) * C);
        m0 = mn0; m1 = mn1;

        float rs0 = 0.f, rs1 = 0.f;
        #pragma unroll
        for (int j = 0; j < 8; j++) {
            s[j][0] = ex2((s[j][0] - m0) * C);
            s[j][1] = ex2((s[j][1] - m0) * C);
            s[j][2] = ex2((s[j][2] - m1) * C);
            s[j][3] = ex2((s[j][3] - m1) * C);
            rs0 += s[j][0] + s[j][1];
            rs1 += s[j][2] + s[j][3];
        }
        rs0 += __shfl_xor_sync(0xFFFFFFFFu, rs0, 1);
        rs0 += __shfl_xor_sync(0xFFFFFFFFu, rs0, 2);
        rs1 += __shfl_xor_sync(0xFFFFFFFFu, rs1, 1);
        rs1 += __shfl_xor_sync(0xFFFFFFFFu, rs1, 2);
        l0 = l0 * a0 + rs0;
        l1 = l1 * a1 + rs1;
        #pragma unroll
        for (int j = 0; j < 8; j++) {
            o[j][0] *= a0; o[j][1] *= a0;
            o[j][2] *= a1; o[j][3] *= a1;
        }

        // ---- P -> split-bf16 A-fragments ----
        uint32_t ph[4][4], pl[4][4];
        #pragma unroll
        for (int kk = 0; kk < 4; kk++) {
            float h00, h01, h10, h11, lo00, lo01, lo10, lo11;
            split1(s[2 * kk][0], h00, lo00); split1(s[2 * kk][1], h01, lo01);
            split1(s[2 * kk][2], h10, lo10); split1(s[2 * kk][3], h11, lo11);
            ph[kk][0] = pack2(h00, h01); pl[kk][0] = pack2(lo00, lo01);
            ph[kk][1] = pack2(h10, h11); pl[kk][1] = pack2(lo10, lo11);
            split1(s[2 * kk + 1][0], h00, lo00); split1(s[2 * kk + 1][1], h01, lo01);
            split1(s[2 * kk + 1][2], h10, lo10); split1(s[2 * kk + 1][3], h11, lo11);
            ph[kk][2] = pack2(h00, h01); pl[kk][2] = pack2(lo00, lo01);
            ph[kk][3] = pack2(h10, h11); pl[kk][3] = pack2(lo10, lo11);
        }

        // ---- O += P V (split, 3 terms) ----
        #pragma unroll
        for (int kk = 0; kk < 4; kk++) {
            uint32_t bhf[4][4], blf[4][4];
            #pragma unroll
            for (int g = 0; g < 4; g++) {
                uint32_t addr = stg + 2 * ATILE + (uint32_t)((kk * 16 + vkr) * KVP) + g * 32 + vnc * 16;
                ldsm_x4_t(bhf[g], addr);
                ldsm_x4_t(blf[g], addr + ATILE);
            }
            #pragma unroll
            for (int g = 0; g < 4; g++)
                #pragma unroll
                for (int h2 = 0; h2 < 2; h2++) {
                    float* d = o[g * 2 + h2];
                    mma_bf16(d, ph[kk], bhf[g][2 * h2], bhf[g][2 * h2 + 1]);
                    mma_bf16(d, ph[kk], blf[g][2 * h2], blf[g][2 * h2 + 1]);
                    mma_bf16(d, pl[kk], bhf[g][2 * h2], bhf[g][2 * h2 + 1]);
                }
        }
        stg_i = (stg_i == 2) ? 0 : stg_i + 1;
        stg_n = (stg_n == 2) ? 0 : stg_n + 1;
    }

    // ---- epilogue ----
    const float inv0 = 1.f / l0, inv1 = 1.f / l1;
    #pragma unroll
    for (int j = 0; j < 8; j++) {
        const int col = j * 8 + 2 * qc;
        float v0 = o[j][0] * inv0, v1 = o[j][1] * inv0;
        float v2 = o[j][2] * inv1, v3 = o[j][3] * inv1;
        float h0, h1, h2, h3, lo0, lo1, lo2, lo3;
        split1(v0, h0, lo0); split1(v1, h1, lo1);
        split1(v2, h2, lo2); split1(v3, h3, lo3);
        *(uint32_t*)(xhi + rowbase + (size_t)r0 * DIM + col) = pack2(h0, h1);
        *(uint32_t*)(xlo + rowbase + (size_t)r0 * DIM + col) = pack2(lo0, lo1);
        *(uint32_t*)(xhi + rowbase + (size_t)r1 * DIM + col) = pack2(h2, h3);
        *(uint32_t*)(xlo + rowbase + (size_t)r1 * DIM + col) = pack2(lo2, lo3);
    }
}

// ---------------- launcher ----------------
extern "C" void kernel_launch(void* const* d_in, const int* in_sizes, int n_in,
                              void* d_out, int out_size) {
    const float* query = (const float*)d_in[0];
    const float* key   = (const float*)d_in[1];
    const float* value = (const float*)d_in[2];
    const float* cond  = (const float*)d_in[3];
    const float* Wq = (const float*)d_in[4];
    const float* bq = (const float*)d_in[5];
    const float* Wk = (const float*)d_in[6];
    const float* bk = (const float*)d_in[7];
    const float* Wv = (const float*)d_in[8];
    const float* bv = (const float*)d_in[9];
    const float* Wo = (const float*)d_in[10];
    const float* bo = (const float*)d_in[11];
    const float* Wc1 = (const float*)d_in[12];
    const float* bc1 = (const float*)d_in[13];
    const float* Wc2 = (const float*)d_in[14];
    float* out = (float*)d_out;

    float *hb, *cb;
    __nv_bfloat16 *ahi, *alo, *whi, *wlo;
    __nv_bfloat16 *qhi, *qlo, *khi, *klo, *vhi, *vlo, *xhi, *xlo;
    cudaGetSymbolAddress((void**)&hb, g_h);
    cudaGetSymbolAddress((void**)&cb, g_c);
    cudaGetSymbolAddress((void**)&ahi, g_ahi);
    cudaGetSymbolAddress((void**)&alo, g_alo);
    cudaGetSymbolAddress((void**)&whi, g_whi);
    cudaGetSymbolAddress((void**)&wlo, g_wlo);
    cudaGetSymbolAddress((void**)&qhi, g_qhi);
    cudaGetSymbolAddress((void**)&qlo, g_qlo);
    cudaGetSymbolAddress((void**)&khi, g_khi);
    cudaGetSymbolAddress((void**)&klo, g_klo);
    cudaGetSymbolAddress((void**)&vhi, g_vhi);
    cudaGetSymbolAddress((void**)&vlo, g_vlo);
    cudaGetSymbolAddress((void**)&xhi, g_xhi);
    cudaGetSymbolAddress((void**)&xlo, g_xlo);

    cudaFuncSetAttribute(gemm_mma,  cudaFuncAttributeMaxDynamicSharedMemorySize, GEMM_SMEM);
    cudaFuncSetAttribute(flash_mma, cudaFuncAttributeMaxDynamicSharedMemorySize, FA_SMEM);

    const int n4 = MROWS * DIM / 4;
    dim3 tgrid(DIM / 32, DIM / 32), tblk(32, 8);
    dim3 ggrid(DIM / 128, MROWS / 128);

    cond_mlp1<<<BATCH, HID>>>(cond, Wc1, bc1, hb);
    cond_mlp2<<<BATCH, DIM>>>(hb, Wc2, cb);

    // Q projection -> split bf16
    split_w_T<<<tgrid, tblk>>>(Wq, whi, wlo);
    split_f32<<<n4 / 256, 256>>>((const float4*)query, ahi, alo, n4);
    gemm_mma<<<ggrid, 256, GEMM_SMEM>>>(ahi, alo, whi, wlo, bq, nullptr, nullptr, qhi, qlo, SEQ);

    // K projection -> split bf16
    split_w_T<<<tgrid, tblk>>>(Wk, whi, wlo);
    split_f32<<<n4 / 256, 256>>>((const float4*)key, ahi, alo, n4);
    gemm_mma<<<ggrid, 256, GEMM_SMEM>>>(ahi, alo, whi, wlo, bk, nullptr, nullptr, khi, klo, SEQ);

    // V projection (+ cond bias) -> split bf16
    split_w_T<<<tgrid, tblk>>>(Wv, whi, wlo);
    split_f32<<<n4 / 256, 256>>>((const float4*)value, ahi, alo, n4);
    gemm_mma<<<ggrid, 256, GEMM_SMEM>>>(ahi, alo, whi, wlo, bv, cb, nullptr, vhi, vlo, SEQ);

    // attention -> split bf16 x
    flash_mma<<<dim3(SEQ / 128, BATCH * HEADS), 256, FA_SMEM>>>(qhi, qlo, khi, klo, vhi, vlo, xhi, xlo);

    // output projection -> fp32 out
    split_w_T<<<tgrid, tblk>>>(Wo, whi, wlo);
    gemm_mma<<<ggrid, 256, GEMM_SMEM>>>(xhi, xlo, whi, wlo, bo, nullptr, out, nullptr, nullptr, SEQ);
}